// round 13
// baseline (speedup 1.0000x reference)
#include <cuda_runtime.h>
#include <cuda_bf16.h>
#include <math.h>
#include <cstdint>

// Problem constants
#define BATCH     2
#define SEQ       2048
#define DMODEL    2048
#define NHEADS    16
#define DK        128
#define MTOT      (BATCH * SEQ)          // 4096
#define LORA_SCALING 2.0f
#define SM_SCALE  0.08838834764831845f   // 1/sqrt(128)
#define NBH       (BATCH * NHEADS)       // 32

// ---------------------------------------------------------------------------
// Scratch buffers
// ---------------------------------------------------------------------------
#define HSZ (BATCH * NHEADS * SEQ * DK)  // 8388608
__device__ float g_t_qkv[MTOT * 24];
__device__ float g_t_o[MTOT * 8];
__device__ float g_ctx[MTOT * DMODEL];
__device__ __nv_bfloat16 g_xhi[MTOT * DMODEL];
__device__ __nv_bfloat16 g_xlo[MTOT * DMODEL];
__device__ __nv_bfloat16 g_whi[4ull * DMODEL * DMODEL];
__device__ __nv_bfloat16 g_wlo[4ull * DMODEL * DMODEL];
__device__ __nv_bfloat16 g_chi[MTOT * DMODEL];
__device__ __nv_bfloat16 g_clo[MTOT * DMODEL];
__device__ __nv_bfloat16 g_qhi[HSZ], g_qlo[HSZ];
__device__ __nv_bfloat16 g_khi[HSZ], g_klo[HSZ];
__device__ __nv_bfloat16 g_vhi[HSZ], g_vlo[HSZ];
__device__ __nv_bfloat16 g_vthi[HSZ], g_vtlo[HSZ];

// ---------------------------------------------------------------------------
// PTX helpers
// ---------------------------------------------------------------------------
__device__ __forceinline__ void cp16(uint32_t sm_dst, const void* g_src) {
    asm volatile("cp.async.cg.shared.global [%0], [%1], 16;" :: "r"(sm_dst), "l"(g_src) : "memory");
}
#define CP_COMMIT() asm volatile("cp.async.commit_group;" ::: "memory")
#define CP_WAIT(n)  asm volatile("cp.async.wait_group %0;" :: "n"(n) : "memory")

__device__ __forceinline__ uint32_t smem_u32(const void* p) {
    uint32_t a;
    asm("{ .reg .u64 t; cvta.to.shared.u64 t, %1; cvt.u32.u64 %0, t; }" : "=r"(a) : "l"(p));
    return a;
}
#define LDSM_X4(r0, r1, r2, r3, addr) \
    asm volatile("ldmatrix.sync.aligned.m8n8.x4.shared.b16 {%0,%1,%2,%3}, [%4];" \
        : "=r"(r0), "=r"(r1), "=r"(r2), "=r"(r3) : "r"(addr))

#define MMA16816(d, a, b) \
    asm volatile("mma.sync.aligned.m16n8k16.row.col.f32.bf16.bf16.f32 " \
        "{%0,%1,%2,%3}, {%4,%5,%6,%7}, {%8,%9}, {%0,%1,%2,%3};" \
        : "+f"((d)[0]), "+f"((d)[1]), "+f"((d)[2]), "+f"((d)[3]) \
        : "r"((a)[0]), "r"((a)[1]), "r"((a)[2]), "r"((a)[3]), \
          "r"((b)[0]), "r"((b)[1]))

__device__ __forceinline__ void split2(float a, float b, uint32_t& hi, uint32_t& lo) {
    __nv_bfloat16 ha = __float2bfloat16_rn(a), hb = __float2bfloat16_rn(b);
    __nv_bfloat16 la = __float2bfloat16_rn(a - __bfloat162float(ha));
    __nv_bfloat16 lb = __float2bfloat16_rn(b - __bfloat162float(hb));
    __nv_bfloat162 H(ha, hb), L(la, lb);
    hi = *(uint32_t*)&H;
    lo = *(uint32_t*)&L;
}

// ---------------------------------------------------------------------------
// fp32 -> bf16 hi/lo split
// ---------------------------------------------------------------------------
__global__ void __launch_bounds__(256)
split_kernel(const float* __restrict__ src, __nv_bfloat16* __restrict__ hi,
             __nv_bfloat16* __restrict__ lo, int n4)
{
    int i = blockIdx.x * 256 + threadIdx.x;
    if (i >= n4) return;
    float4 v = ((const float4*)src)[i];
    __nv_bfloat16 h0 = __float2bfloat16_rn(v.x);
    __nv_bfloat16 h1 = __float2bfloat16_rn(v.y);
    __nv_bfloat16 h2 = __float2bfloat16_rn(v.z);
    __nv_bfloat16 h3 = __float2bfloat16_rn(v.w);
    __nv_bfloat16 l0 = __float2bfloat16_rn(v.x - __bfloat162float(h0));
    __nv_bfloat16 l1 = __float2bfloat16_rn(v.y - __bfloat162float(h1));
    __nv_bfloat16 l2 = __float2bfloat16_rn(v.z - __bfloat162float(h2));
    __nv_bfloat16 l3 = __float2bfloat16_rn(v.w - __bfloat162float(h3));
    __nv_bfloat162* hp = (__nv_bfloat162*)(hi + (size_t)i * 4);
    __nv_bfloat162* lp = (__nv_bfloat162*)(lo + (size_t)i * 4);
    hp[0] = __nv_bfloat162(h0, h1); hp[1] = __nv_bfloat162(h2, h3);
    lp[0] = __nv_bfloat162(l0, l1); lp[1] = __nv_bfloat162(l2, l3);
}

// ---------------------------------------------------------------------------
// LoRA intermediate T[m][o] = sum_k X[m][k] * A_(o/8)[o%8][k]
// ---------------------------------------------------------------------------
template <int NOUT>
__global__ void __launch_bounds__(256)
lora_kernel(const float* __restrict__ X,
            const float* __restrict__ A0, const float* __restrict__ A1,
            const float* __restrict__ A2, float* __restrict__ T)
{
    __shared__ float sA[NOUT * 512];
    const int tid   = threadIdx.x;
    const int row   = tid >> 4;          // 0..15
    const int slice = tid & 15;          // 0..15
    const int m     = blockIdx.x * 16 + row;
    const float* Aps[3] = {A0, A1, A2};

    float acc[NOUT];
#pragma unroll
    for (int o = 0; o < NOUT; o++) acc[o] = 0.0f;

    for (int c = 0; c < 4; c++) {
        const int k0 = c * 512;
        for (int i = tid; i < NOUT * 512; i += 256) {
            int o = i >> 9, kk = i & 511;
            const float* Ap = Aps[o >> 3];
            sA[i] = Ap[(o & 7) * DMODEL + k0 + kk];
        }
        __syncthreads();
        const float* xr = X + (size_t)m * DMODEL + k0;
#pragma unroll 4
        for (int j = 0; j < 32; j++) {
            int kk = slice + j * 16;
            float xv = xr[kk];
#pragma unroll
            for (int o = 0; o < NOUT; o++) acc[o] += xv * sA[o * 512 + kk];
        }
        __syncthreads();
    }
#pragma unroll
    for (int o = 0; o < NOUT; o++) {
        float v = acc[o];
        v += __shfl_xor_sync(0xffffffffu, v, 1);
        v += __shfl_xor_sync(0xffffffffu, v, 2);
        v += __shfl_xor_sync(0xffffffffu, v, 4);
        v += __shfl_xor_sync(0xffffffffu, v, 8);
        if (slice == 0) T[(size_t)m * NOUT + o] = v;
    }
}

// ---------------------------------------------------------------------------
// mma.sync GEMM (R11: ldmatrix fragment loads). 128x128 tile, 8 warps,
// K-block 64, two-stage cp.async.
// MODE 0: single matrix, fp32 out. MODE 1: FUSED QKV (N=6144).
// ---------------------------------------------------------------------------
#define GKB        64
#define ROWB       144
#define MAT_BYTES  (128 * ROWB)          // 18432
#define STAGE_B    (4 * MAT_BYTES)       // 73728 (Ahi|Alo|Whi|Wlo)
#define GEMM_SMEM  (2 * STAGE_B)         // 147456
#define NKITER     (DMODEL / GKB)        // 32

__device__ __forceinline__ void gemm_load_stage(
    uint32_t sbase, int tid, int s,
    const __nv_bfloat16* gAh, const __nv_bfloat16* gAl,
    const __nv_bfloat16* gBh, const __nv_bfloat16* gBl)
{
    const uint32_t base = sbase + (s & 1) * STAGE_B;
    const int kt = s * GKB;
    const __nv_bfloat16* srcs[4] = {gAh, gAl, gBh, gBl};
#pragma unroll
    for (int mat = 0; mat < 4; mat++) {
        const __nv_bfloat16* g = srcs[mat];
        uint32_t mbase = base + mat * MAT_BYTES;
#pragma unroll
        for (int t = 0; t < 4; t++) {
            int chunk = tid + t * 256;
            int row = chunk >> 3;
            int cc  = chunk & 7;
            cp16(mbase + row * ROWB + cc * 16,
                 g + (size_t)row * DMODEL + kt + cc * 8);
        }
    }
    CP_COMMIT();
}

template <int MODE>
__global__ void __launch_bounds__(256)
gemm_mma_kernel(const __nv_bfloat16* __restrict__ Ahi, const __nv_bfloat16* __restrict__ Alo,
                const __nv_bfloat16* __restrict__ Bhi, const __nv_bfloat16* __restrict__ Blo,
                const float* __restrict__ bias0, const float* __restrict__ bias1,
                const float* __restrict__ bias2,
                const float* __restrict__ T,
                const float* __restrict__ Bm0, const float* __restrict__ Bm1,
                const float* __restrict__ Bm2,
                float* __restrict__ YoutF,
                __nv_bfloat16* __restrict__ YH0, __nv_bfloat16* __restrict__ YL0,
                __nv_bfloat16* __restrict__ YH1, __nv_bfloat16* __restrict__ YL1,
                __nv_bfloat16* __restrict__ YH2, __nv_bfloat16* __restrict__ YL2,
                int tstride)
{
    extern __shared__ __align__(16) char smem[];
    uint32_t sbase = smem_u32(smem);
    const int tid  = threadIdx.x;
    const int wid  = tid >> 5;
    const int lane = tid & 31;
    const int g    = lane >> 2;
    const int t4   = lane & 3;
    const int wm   = (wid & 1) * 64;
    const int wn   = (wid >> 1) * 32;
    const int m0  = blockIdx.y * 128;
    const int n0g = blockIdx.x * 128;
    const int mat = (MODE == 1) ? (n0g >> 11) : 0;
    const int n0  = n0g & 2047;
    const int toff = (MODE == 1) ? mat * 8 : 0;

    const float* biasP = (mat == 0) ? bias0 : (mat == 1) ? bias1 : bias2;
    const float* BmP   = (mat == 0) ? Bm0   : (mat == 1) ? Bm1   : Bm2;
    __nv_bfloat16* YH  = (mat == 0) ? YH0 : (mat == 1) ? YH1 : YH2;
    __nv_bfloat16* YL  = (mat == 0) ? YL0 : (mat == 1) ? YL1 : YL2;

    const int lrow = lane & 7;
    const uint32_t aLane = (uint32_t)((wm + ((lane >> 3) & 1) * 8 + lrow) * ROWB + (lane >> 4) * 16);
    const uint32_t bLane = (uint32_t)((wn + ((lane >> 4) & 1) * 8 + lrow) * ROWB + ((lane >> 3) & 1) * 16);

    const __nv_bfloat16* gAh = Ahi + (size_t)m0 * DMODEL;
    const __nv_bfloat16* gAl = Alo + (size_t)m0 * DMODEL;
    const __nv_bfloat16* gBh = Bhi + (size_t)n0g * DMODEL;
    const __nv_bfloat16* gBl = Blo + (size_t)n0g * DMODEL;

    float acc[4][4][4];
#pragma unroll
    for (int i = 0; i < 4; i++)
#pragma unroll
        for (int j = 0; j < 4; j++)
#pragma unroll
            for (int r = 0; r < 4; r++) acc[i][j][r] = 0.0f;

    gemm_load_stage(sbase, tid, 0, gAh, gAl, gBh, gBl);
    gemm_load_stage(sbase, tid, 1, gAh, gAl, gBh, gBl);

    for (int s = 0; s < NKITER; s++) {
        if (s == NKITER - 1) { CP_WAIT(0); } else { CP_WAIT(1); }
        __syncthreads();

        const uint32_t st = sbase + (s & 1) * STAGE_B;
        const uint32_t aHiA = st + aLane;
        const uint32_t aLoA = aHiA + MAT_BYTES;
        const uint32_t bHiA = st + 2 * MAT_BYTES + bLane;
        const uint32_t bLoA = bHiA + MAT_BYTES;

#pragma unroll
        for (int kh = 0; kh < 4; kh++) {
            const uint32_t ko = kh * 32;
            uint32_t ah[4][4], al[4][4], bh[4][2], bl[4][2];
#pragma unroll
            for (int mi = 0; mi < 4; mi++)
                LDSM_X4(ah[mi][0], ah[mi][1], ah[mi][2], ah[mi][3],
                        aHiA + mi * (16 * ROWB) + ko);
#pragma unroll
            for (int p = 0; p < 2; p++)
                LDSM_X4(bh[2 * p][0], bh[2 * p][1], bh[2 * p + 1][0], bh[2 * p + 1][1],
                        bHiA + p * (16 * ROWB) + ko);
#pragma unroll
            for (int mi = 0; mi < 4; mi++)
#pragma unroll
                for (int ni = 0; ni < 4; ni++)
                    MMA16816(acc[mi][ni], ah[mi], bh[ni]);

#pragma unroll
            for (int p = 0; p < 2; p++)
                LDSM_X4(bl[2 * p][0], bl[2 * p][1], bl[2 * p + 1][0], bl[2 * p + 1][1],
                        bLoA + p * (16 * ROWB) + ko);
#pragma unroll
            for (int mi = 0; mi < 4; mi++)
#pragma unroll
                for (int ni = 0; ni < 4; ni++)
                    MMA16816(acc[mi][ni], ah[mi], bl[ni]);

#pragma unroll
            for (int mi = 0; mi < 4; mi++)
                LDSM_X4(al[mi][0], al[mi][1], al[mi][2], al[mi][3],
                        aLoA + mi * (16 * ROWB) + ko);
#pragma unroll
            for (int mi = 0; mi < 4; mi++)
#pragma unroll
                for (int ni = 0; ni < 4; ni++)
                    MMA16816(acc[mi][ni], al[mi], bh[ni]);
        }

        __syncthreads();
        if (s + 2 < NKITER)
            gemm_load_stage(sbase, tid, s + 2, gAh, gAl, gBh, gBl);
    }

    // Epilogue
    __syncthreads();
    float* sT = (float*)smem;
    float* sB = (float*)(smem + 4096);
    {
        int row = tid >> 1;
        int half = tid & 1;
        float4 tv = *(const float4*)&T[(size_t)(m0 + row) * tstride + toff + half * 4];
        *(float4*)&sT[row * 8 + half * 4] = tv;
        float4 bv = *(const float4*)&BmP[(size_t)(n0 + row) * 8 + half * 4];
        *(float4*)&sB[row * 8 + half * 4] = bv;
    }
    __syncthreads();

#pragma unroll
    for (int mi = 0; mi < 4; mi++) {
        int rl0 = wm + mi * 16 + g;
#pragma unroll
        for (int rr = 0; rr < 2; rr++) {
            int rl = rl0 + rr * 8;
            int m = m0 + rl;
            const float* tr = &sT[rl * 8];
#pragma unroll
            for (int ni = 0; ni < 4; ni++) {
                int cl = wn + ni * 8 + t4 * 2;
                int n = n0 + cl;
                float d0 = acc[mi][ni][rr * 2 + 0];
                float d1 = acc[mi][ni][rr * 2 + 1];
                const float* b0 = &sB[cl * 8];
                const float* b1 = &sB[(cl + 1) * 8];
                float dot0 = 0.0f, dot1 = 0.0f;
#pragma unroll
                for (int r = 0; r < 8; r++) { dot0 += tr[r] * b0[r]; dot1 += tr[r] * b1[r]; }
                float yx = d0 + biasP[n]     + LORA_SCALING * dot0;
                float yy = d1 + biasP[n + 1] + LORA_SCALING * dot1;
                if (MODE == 0) {
                    *(float2*)&YoutF[(size_t)m * DMODEL + n] = make_float2(yx, yy);
                } else {
                    int bb = m >> 11, ss = m & 2047;
                    int h = n >> 7, d = n & 127;
                    size_t idx = ((((size_t)bb * NHEADS + h) * SEQ + ss) << 7) + d;
                    uint32_t hv, lv;
                    split2(yx, yy, hv, lv);
                    *(uint32_t*)&YH[idx] = hv;
                    *(uint32_t*)&YL[idx] = lv;
                }
            }
        }
    }
}

// ---------------------------------------------------------------------------
// V transpose: [bh][s][d] -> [bh][d][s], hi and lo.
// ---------------------------------------------------------------------------
__global__ void __launch_bounds__(256)
vtrans_kernel(const __nv_bfloat16* __restrict__ vh, const __nv_bfloat16* __restrict__ vl,
              __nv_bfloat16* __restrict__ vth, __nv_bfloat16* __restrict__ vtl)
{
    __shared__ __nv_bfloat16 tile[64][65];
    const int tid = threadIdx.x;
    const int bh = blockIdx.z;
    const int s0 = blockIdx.x * 64;
    const int d0 = blockIdx.y * 64;

    const __nv_bfloat16* srcs[2] = {vh, vl};
    __nv_bfloat16* dsts[2] = {vth, vtl};

#pragma unroll
    for (int pass = 0; pass < 2; pass++) {
        const __nv_bfloat16* src = srcs[pass] + ((size_t)bh * SEQ + s0) * DK + d0;
        __nv_bfloat16* dst = dsts[pass] + ((size_t)bh * DK + d0) * SEQ + s0;
        {
            int i = tid >> 2;
            int jp = tid & 3;
#pragma unroll
            for (int c = 0; c < 8; c++) {
                int j2 = jp * 8 + c;
                __nv_bfloat162 v = *(const __nv_bfloat162*)(src + (size_t)i * DK + j2 * 2);
                tile[i][j2 * 2] = v.x;
                tile[i][j2 * 2 + 1] = v.y;
            }
        }
        __syncthreads();
        {
            int r = tid >> 5;
            int wp = tid & 31;
#pragma unroll
            for (int p = 0; p < 8; p++) {
                int row = r + p * 8;
                __nv_bfloat162 v(tile[2 * wp][row], tile[2 * wp + 1][row]);
                *(__nv_bfloat162*)(dst + (size_t)row * SEQ + 2 * wp) = v;
            }
        }
        __syncthreads();
    }
}

// ---------------------------------------------------------------------------
// Flash attention (mma.sync hi/lo, ldmatrix fragment loads). fp32 ctx out.
// ---------------------------------------------------------------------------
#define FQROW  272
#define FQSZ   (128 * FQROW)
#define FQSZ2  (2 * FQSZ)
#define FKSZ   (64 * FQROW)
#define FVROW  144
#define FVSZ   (128 * FVROW)
#define FSTAGE (2 * FKSZ + 2 * FVSZ)
#define FLASH_SMEM (FQSZ2 + 2 * FSTAGE)  // 212992
#define NKVT   (SEQ / 64)

__device__ __forceinline__ void flash_load_stage(
    uint32_t sbase, int tid, int j,
    const __nv_bfloat16* Kh, const __nv_bfloat16* Kl,
    const __nv_bfloat16* VTh, const __nv_bfloat16* VTl)
{
    const uint32_t st = sbase + FQSZ2 + (j & 1) * FSTAGE;
    const int kv0 = j * 64;
#pragma unroll
    for (int w = 0; w < 4; w++) {
        int chunk = tid + w * 256;
        int row = chunk >> 4;
        int c   = chunk & 15;
        size_t go = (size_t)(kv0 + row) * DK + c * 8;
        cp16(st + row * FQROW + c * 16, Kh + go);
        cp16(st + FKSZ + row * FQROW + c * 16, Kl + go);
    }
#pragma unroll
    for (int w = 0; w < 4; w++) {
        int chunk = tid + w * 256;
        int row = chunk >> 3;
        int c   = chunk & 7;
        size_t go = (size_t)row * SEQ + kv0 + c * 8;
        cp16(st + 2 * FKSZ + row * FVROW + c * 16, VTh + go);
        cp16(st + 2 * FKSZ + FVSZ + row * FVROW + c * 16, VTl + go);
    }
    CP_COMMIT();
}

__global__ void __launch_bounds__(256)
flash_mma_kernel(const __nv_bfloat16* __restrict__ Qhi, const __nv_bfloat16* __restrict__ Qlo,
                 const __nv_bfloat16* __restrict__ Khi, const __nv_bfloat16* __restrict__ Klo,
                 const __nv_bfloat16* __restrict__ VThi, const __nv_bfloat16* __restrict__ VTlo,
                 float* __restrict__ CTX)
{
    extern __shared__ __align__(16) char smem[];
    uint32_t sbase = smem_u32(smem);
    const int tid  = threadIdx.x;
    const int wid  = tid >> 5;
    const int lane = tid & 31;
    const int g    = lane >> 2;
    const int t4   = lane & 3;
    const int wm   = wid * 16;
    const int bh = blockIdx.y;
    const int q0 = blockIdx.x * 128;

    // ldmatrix lane address components (same mapping verified in gemm R11)
    const int lrow = lane & 7;
    const uint32_t qLane = (uint32_t)((wm + ((lane >> 3) & 1) * 8 + lrow) * FQROW + (lane >> 4) * 16);
    const uint32_t kLane = (uint32_t)((((lane >> 4) & 1) * 8 + lrow) * FQROW + ((lane >> 3) & 1) * 16);
    const uint32_t vLane = (uint32_t)((((lane >> 4) & 1) * 8 + lrow) * FVROW + ((lane >> 3) & 1) * 16);

    const __nv_bfloat16* Qh = Qhi + ((size_t)bh * SEQ + q0) * DK;
    const __nv_bfloat16* Ql = Qlo + ((size_t)bh * SEQ + q0) * DK;
    const __nv_bfloat16* Kh = Khi + (size_t)bh * SEQ * DK;
    const __nv_bfloat16* Kl = Klo + (size_t)bh * SEQ * DK;
    const __nv_bfloat16* Vh = VThi + (size_t)bh * DK * SEQ;
    const __nv_bfloat16* Vl = VTlo + (size_t)bh * DK * SEQ;

#pragma unroll
    for (int w = 0; w < 8; w++) {
        int chunk = tid + w * 256;
        int row = chunk >> 4;
        int c   = chunk & 15;
        size_t go = (size_t)row * DK + c * 8;
        cp16(sbase + row * FQROW + c * 16, Qh + go);
        cp16(sbase + FQSZ + row * FQROW + c * 16, Ql + go);
    }
    flash_load_stage(sbase, tid, 0, Kh, Kl, Vh, Vl);
    flash_load_stage(sbase, tid, 1, Kh, Kl, Vh, Vl);

    float m0 = -INFINITY, m1 = -INFINITY, l0 = 0.0f, l1 = 0.0f;
    float oacc[16][4];
#pragma unroll
    for (int i = 0; i < 16; i++)
#pragma unroll
        for (int r = 0; r < 4; r++) oacc[i][r] = 0.0f;

    for (int j = 0; j < NKVT; j++) {
        if (j == NKVT - 1) { CP_WAIT(0); } else { CP_WAIT(1); }
        __syncthreads();
        const uint32_t st = sbase + FQSZ2 + (j & 1) * FSTAGE;

        float sacc[8][4];
#pragma unroll
        for (int nb = 0; nb < 8; nb++)
#pragma unroll
            for (int r = 0; r < 4; r++) sacc[nb][r] = 0.0f;

        // ---- QK: per k16, ldmatrix Q (hi+lo) and K pairs ----
#pragma unroll
        for (int kb = 0; kb < 8; kb++) {
            const uint32_t ko = kb * 32;
            uint32_t qh[4], ql[4];
            LDSM_X4(qh[0], qh[1], qh[2], qh[3], sbase + qLane + ko);
            LDSM_X4(ql[0], ql[1], ql[2], ql[3], sbase + FQSZ + qLane + ko);
#pragma unroll
            for (int p = 0; p < 4; p++) {
                uint32_t bhF[2][2], blF[2][2];
                uint32_t ka = st + kLane + p * (16 * FQROW) + ko;
                LDSM_X4(bhF[0][0], bhF[0][1], bhF[1][0], bhF[1][1], ka);
                LDSM_X4(blF[0][0], blF[0][1], blF[1][0], blF[1][1], ka + FKSZ);
#pragma unroll
                for (int q = 0; q < 2; q++) {
                    int nb = 2 * p + q;
                    MMA16816(sacc[nb], qh, bhF[q]);
                    MMA16816(sacc[nb], qh, blF[q]);
                    MMA16816(sacc[nb], ql, bhF[q]);
                }
            }
        }

        float mx0 = -INFINITY, mx1 = -INFINITY;
#pragma unroll
        for (int nb = 0; nb < 8; nb++) {
#pragma unroll
            for (int r = 0; r < 4; r++) sacc[nb][r] *= SM_SCALE;
            mx0 = fmaxf(mx0, fmaxf(sacc[nb][0], sacc[nb][1]));
            mx1 = fmaxf(mx1, fmaxf(sacc[nb][2], sacc[nb][3]));
        }
        mx0 = fmaxf(mx0, __shfl_xor_sync(0xffffffffu, mx0, 1));
        mx0 = fmaxf(mx0, __shfl_xor_sync(0xffffffffu, mx0, 2));
        mx1 = fmaxf(mx1, __shfl_xor_sync(0xffffffffu, mx1, 1));
        mx1 = fmaxf(mx1, __shfl_xor_sync(0xffffffffu, mx1, 2));

        float mn0 = fmaxf(m0, mx0), mn1 = fmaxf(m1, mx1);
        float sc0 = __expf(m0 - mn0), sc1 = __expf(m1 - mn1);
        m0 = mn0; m1 = mn1;

        float rs0 = 0.0f, rs1 = 0.0f;
#pragma unroll
        for (int nb = 0; nb < 8; nb++) {
            float p0 = __expf(sacc[nb][0] - mn0);
            float p1 = __expf(sacc[nb][1] - mn0);
            float p2 = __expf(sacc[nb][2] - mn1);
            float p3 = __expf(sacc[nb][3] - mn1);
            sacc[nb][0] = p0; sacc[nb][1] = p1; sacc[nb][2] = p2; sacc[nb][3] = p3;
            rs0 += p0 + p1; rs1 += p2 + p3;
        }
        rs0 += __shfl_xor_sync(0xffffffffu, rs0, 1);
        rs0 += __shfl_xor_sync(0xffffffffu, rs0, 2);
        rs1 += __shfl_xor_sync(0xffffffffu, rs1, 1);
        rs1 += __shfl_xor_sync(0xffffffffu, rs1, 2);
        l0 = l0 * sc0 + rs0;
        l1 = l1 * sc1 + rs1;

#pragma unroll
        for (int nb = 0; nb < 16; nb++) {
            oacc[nb][0] *= sc0; oacc[nb][1] *= sc0;
            oacc[nb][2] *= sc1; oacc[nb][3] *= sc1;
        }

        uint32_t ph[4][4], pl[4][4];
#pragma unroll
        for (int kb = 0; kb < 4; kb++) {
            split2(sacc[2 * kb][0],     sacc[2 * kb][1],     ph[kb][0], pl[kb][0]);
            split2(sacc[2 * kb][2],     sacc[2 * kb][3],     ph[kb][1], pl[kb][1]);
            split2(sacc[2 * kb + 1][0], sacc[2 * kb + 1][1], ph[kb][2], pl[kb][2]);
            split2(sacc[2 * kb + 1][2], sacc[2 * kb + 1][3], ph[kb][3], pl[kb][3]);
        }

        // ---- PV: per k16, ldmatrix V pairs ----
        const uint32_t vb = st + 2 * FKSZ;
#pragma unroll
        for (int kb = 0; kb < 4; kb++) {
            const uint32_t ko = kb * 32;
#pragma unroll
            for (int p = 0; p < 8; p++) {
                uint32_t bhF[2][2], blF[2][2];
                uint32_t va = vb + vLane + p * (16 * FVROW) + ko;
                LDSM_X4(bhF[0][0], bhF[0][1], bhF[1][0], bhF[1][1], va);
                LDSM_X4(blF[0][0], blF[0][1], blF[1][0], blF[1][1], va + FVSZ);
#pragma unroll
                for (int q = 0; q < 2; q++) {
                    int nb = 2 * p + q;
                    MMA16816(oacc[nb], ph[kb], bhF[q]);
                    MMA16816(oacc[nb], ph[kb], blF[q]);
                    MMA16816(oacc[nb], pl[kb], bhF[q]);
                }
            }
        }

        __syncthreads();
        if (j + 2 < NKVT)
            flash_load_stage(sbase, tid, j + 2, Kh, Kl, Vh, Vl);
    }

    // write ctx fp32 token-major: [b*S+s][h*128+d]
    const int b = bh >> 4;
    const int h = bh & 15;
    const float inv0 = 1.0f / l0;
    const float inv1 = 1.0f / l1;
    const int s0r = q0 + wm + g;
    float* o0 = &CTX[((size_t)(b * SEQ + s0r)) * DMODEL + h * DK];
    float* o1 = &CTX[((size_t)(b * SEQ + s0r + 8)) * DMODEL + h * DK];
#pragma unroll
    for (int nb = 0; nb < 16; nb++) {
        int d = nb * 8 + t4 * 2;
        *(float2*)&o0[d] = make_float2(oacc[nb][0] * inv0, oacc[nb][1] * inv0);
        *(float2*)&o1[d] = make_float2(oacc[nb][2] * inv1, oacc[nb][3] * inv1);
    }
}

// ---------------------------------------------------------------------------
// Launch
// ---------------------------------------------------------------------------
extern "C" void kernel_launch(void* const* d_in, const int* in_sizes, int n_in,
                              void* d_out, int out_size)
{
    const float* x  = (const float*)d_in[0];
    const float* Wq = (const float*)d_in[1];
    const float* bq = (const float*)d_in[2];
    const float* Aq = (const float*)d_in[3];
    const float* Bq = (const float*)d_in[4];
    const float* Wk = (const float*)d_in[5];
    const float* bk = (const float*)d_in[6];
    const float* Ak = (const float*)d_in[7];
    const float* Bk = (const float*)d_in[8];
    const float* Wv = (const float*)d_in[9];
    const float* bv = (const float*)d_in[10];
    const float* Av = (const float*)d_in[11];
    const float* Bv = (const float*)d_in[12];
    const float* Wo = (const float*)d_in[13];
    const float* bo = (const float*)d_in[14];
    const float* Ao = (const float*)d_in[15];
    const float* Bo = (const float*)d_in[16];
    float* out = (float*)d_out;

    float *pt, *pto, *pctx;
    __nv_bfloat16 *pxhi, *pxlo, *pwhi, *pwlo, *pchi, *pclo;
    __nv_bfloat16 *pqhi, *pqlo, *pkhi, *pklo, *pvhi, *pvlo, *pvthi, *pvtlo;
    cudaGetSymbolAddress((void**)&pt,   g_t_qkv);
    cudaGetSymbolAddress((void**)&pto,  g_t_o);
    cudaGetSymbolAddress((void**)&pctx, g_ctx);
    cudaGetSymbolAddress((void**)&pxhi, g_xhi);
    cudaGetSymbolAddress((void**)&pxlo, g_xlo);
    cudaGetSymbolAddress((void**)&pwhi, g_whi);
    cudaGetSymbolAddress((void**)&pwlo, g_wlo);
    cudaGetSymbolAddress((void**)&pchi, g_chi);
    cudaGetSymbolAddress((void**)&pclo, g_clo);
    cudaGetSymbolAddress((void**)&pqhi, g_qhi);
    cudaGetSymbolAddress((void**)&pqlo, g_qlo);
    cudaGetSymbolAddress((void**)&pkhi, g_khi);
    cudaGetSymbolAddress((void**)&pklo, g_klo);
    cudaGetSymbolAddress((void**)&pvhi, g_vhi);
    cudaGetSymbolAddress((void**)&pvlo, g_vlo);
    cudaGetSymbolAddress((void**)&pvthi, g_vthi);
    cudaGetSymbolAddress((void**)&pvtlo, g_vtlo);

    cudaFuncSetAttribute(gemm_mma_kernel<0>,
                         cudaFuncAttributeMaxDynamicSharedMemorySize, GEMM_SMEM);
    cudaFuncSetAttribute(gemm_mma_kernel<1>,
                         cudaFuncAttributeMaxDynamicSharedMemorySize, GEMM_SMEM);
    cudaFuncSetAttribute(flash_mma_kernel,
                         cudaFuncAttributeMaxDynamicSharedMemorySize, FLASH_SMEM);

    const size_t WSZ = (size_t)DMODEL * DMODEL;
    const int nX4 = MTOT * DMODEL / 4;
    const int nW4 = (int)(WSZ / 4);
    const int sg  = 256;

    // 1) Splits (Wq|Wk|Wv contiguous -> fused GEMM B operand)
    split_kernel<<<(nX4 + sg - 1) / sg, sg>>>(x, pxhi, pxlo, nX4);
    split_kernel<<<(nW4 + sg - 1) / sg, sg>>>(Wq, pwhi + 0 * WSZ, pwlo + 0 * WSZ, nW4);
    split_kernel<<<(nW4 + sg - 1) / sg, sg>>>(Wk, pwhi + 1 * WSZ, pwlo + 1 * WSZ, nW4);
    split_kernel<<<(nW4 + sg - 1) / sg, sg>>>(Wv, pwhi + 2 * WSZ, pwlo + 2 * WSZ, nW4);
    split_kernel<<<(nW4 + sg - 1) / sg, sg>>>(Wo, pwhi + 3 * WSZ, pwlo + 3 * WSZ, nW4);

    // 2) LoRA intermediates (q|k|v)
    lora_kernel<24><<<MTOT / 16, 256>>>(x, Aq, Ak, Av, pt);

    // 3) FUSED QKV projection: one GEMM, N = 6144
    dim3 gQKV(3 * DMODEL / 128, MTOT / 128);   // (48, 32) = 1536 blocks
    gemm_mma_kernel<1><<<gQKV, 256, GEMM_SMEM>>>(
        pxhi, pxlo, pwhi, pwlo,
        bq, bk, bv, pt, Bq, Bk, Bv,
        nullptr,
        pqhi, pqlo, pkhi, pklo, pvhi, pvlo, 24);

    // 4) V transpose
    dim3 tgrid(SEQ / 64, DK / 64, NBH);
    vtrans_kernel<<<tgrid, 256>>>(pvhi, pvlo, pvthi, pvtlo);

    // 5) Flash attention -> fp32 ctx
    dim3 fgrid(SEQ / 128, NBH);
    flash_mma_kernel<<<fgrid, 256, FLASH_SMEM>>>(pqhi, pqlo, pkhi, pklo, pvthi, pvtlo, pctx);

    // 6) Output projection
    split_kernel<<<(nX4 + sg - 1) / sg, sg>>>(pctx, pchi, pclo, nX4);
    lora_kernel<8><<<MTOT / 16, 256>>>(pctx, Ao, Ao, Ao, pto);
    dim3 gO(DMODEL / 128, MTOT / 128);         // (16, 32)
    gemm_mma_kernel<0><<<gO, 256, GEMM_SMEM>>>(
        pchi, pclo, pwhi + 3 * WSZ, pwlo + 3 * WSZ,
        bo, bo, bo, pto, Bo, Bo, Bo,
        out,
        nullptr, nullptr, nullptr, nullptr, nullptr, nullptr, 8);
}

// round 14
// speedup vs baseline: 1.2238x; 1.2238x over previous
#include <cuda_runtime.h>
#include <cuda_fp16.h>
#include <math.h>
#include <cstdint>

// Problem constants
#define BATCH     2
#define SEQ       2048
#define DMODEL    2048
#define NHEADS    16
#define DK        128
#define MTOT      (BATCH * SEQ)          // 4096
#define LORA_SCALING 2.0f
#define SM_SCALE  0.08838834764831845f   // 1/sqrt(128)
#define NBH       (BATCH * NHEADS)       // 32

// ---------------------------------------------------------------------------
// Scratch buffers (fp16 hi/lo)
// ---------------------------------------------------------------------------
#define HSZ (BATCH * NHEADS * SEQ * DK)  // 8388608
__device__ float g_t_qkv[MTOT * 24];
__device__ float g_t_o[MTOT * 8];
__device__ float g_ctx[MTOT * DMODEL];
__device__ __half g_xhi[MTOT * DMODEL];
__device__ __half g_xlo[MTOT * DMODEL];
__device__ __half g_whi[4ull * DMODEL * DMODEL];   // hi only (2-product GEMM)
__device__ __half g_chi[MTOT * DMODEL];
__device__ __half g_clo[MTOT * DMODEL];
__device__ __half g_qhi[HSZ], g_qlo[HSZ];
__device__ __half g_khi[HSZ], g_klo[HSZ];
__device__ __half g_vhi[HSZ], g_vlo[HSZ];
__device__ __half g_vthi[HSZ], g_vtlo[HSZ];

// ---------------------------------------------------------------------------
// PTX helpers
// ---------------------------------------------------------------------------
__device__ __forceinline__ void cp16(uint32_t sm_dst, const void* g_src) {
    asm volatile("cp.async.cg.shared.global [%0], [%1], 16;" :: "r"(sm_dst), "l"(g_src) : "memory");
}
#define CP_COMMIT() asm volatile("cp.async.commit_group;" ::: "memory")
#define CP_WAIT(n)  asm volatile("cp.async.wait_group %0;" :: "n"(n) : "memory")

__device__ __forceinline__ uint32_t smem_u32(const void* p) {
    uint32_t a;
    asm("{ .reg .u64 t; cvta.to.shared.u64 t, %1; cvt.u32.u64 %0, t; }" : "=r"(a) : "l"(p));
    return a;
}
#define LDSM_X4(r0, r1, r2, r3, addr) \
    asm volatile("ldmatrix.sync.aligned.m8n8.x4.shared.b16 {%0,%1,%2,%3}, [%4];" \
        : "=r"(r0), "=r"(r1), "=r"(r2), "=r"(r3) : "r"(addr))

#define MMA16816(d, a, b) \
    asm volatile("mma.sync.aligned.m16n8k16.row.col.f32.f16.f16.f32 " \
        "{%0,%1,%2,%3}, {%4,%5,%6,%7}, {%8,%9}, {%0,%1,%2,%3};" \
        : "+f"((d)[0]), "+f"((d)[1]), "+f"((d)[2]), "+f"((d)[3]) \
        : "r"((a)[0]), "r"((a)[1]), "r"((a)[2]), "r"((a)[3]), \
          "r"((b)[0]), "r"((b)[1]))

__device__ __forceinline__ void split2(float a, float b, uint32_t& hi, uint32_t& lo) {
    __half ha = __float2half_rn(a), hb = __float2half_rn(b);
    __half la = __float2half_rn(a - __half2float(ha));
    __half lb = __float2half_rn(b - __half2float(hb));
    __half2 H = __halves2half2(ha, hb), L = __halves2half2(la, lb);
    hi = *(uint32_t*)&H;
    lo = *(uint32_t*)&L;
}

// ---------------------------------------------------------------------------
// fp32 -> fp16 hi/lo split
// ---------------------------------------------------------------------------
__global__ void __launch_bounds__(256)
split_kernel(const float* __restrict__ src, __half* __restrict__ hi,
             __half* __restrict__ lo, int n4)
{
    int i = blockIdx.x * 256 + threadIdx.x;
    if (i >= n4) return;
    float4 v = ((const float4*)src)[i];
    uint32_t h0, l0, h1, l1;
    split2(v.x, v.y, h0, l0);
    split2(v.z, v.w, h1, l1);
    uint32_t* hp = (uint32_t*)(hi + (size_t)i * 4);
    uint32_t* lp = (uint32_t*)(lo + (size_t)i * 4);
    hp[0] = h0; hp[1] = h1;
    lp[0] = l0; lp[1] = l1;
}

// fp32 -> fp16 (hi only, for weights)
__global__ void __launch_bounds__(256)
split_hi_kernel(const float* __restrict__ src, __half* __restrict__ hi, int n4)
{
    int i = blockIdx.x * 256 + threadIdx.x;
    if (i >= n4) return;
    float4 v = ((const float4*)src)[i];
    __half2 a = __halves2half2(__float2half_rn(v.x), __float2half_rn(v.y));
    __half2 b = __halves2half2(__float2half_rn(v.z), __float2half_rn(v.w));
    uint32_t* hp = (uint32_t*)(hi + (size_t)i * 4);
    hp[0] = *(uint32_t*)&a;
    hp[1] = *(uint32_t*)&b;
}

// ---------------------------------------------------------------------------
// LoRA intermediate T[m][o] = sum_k X[m][k] * A_(o/8)[o%8][k]
// ---------------------------------------------------------------------------
template <int NOUT>
__global__ void __launch_bounds__(256)
lora_kernel(const float* __restrict__ X,
            const float* __restrict__ A0, const float* __restrict__ A1,
            const float* __restrict__ A2, float* __restrict__ T)
{
    __shared__ float sA[NOUT * 512];
    const int tid   = threadIdx.x;
    const int row   = tid >> 4;
    const int slice = tid & 15;
    const int m     = blockIdx.x * 16 + row;
    const float* Aps[3] = {A0, A1, A2};

    float acc[NOUT];
#pragma unroll
    for (int o = 0; o < NOUT; o++) acc[o] = 0.0f;

    for (int c = 0; c < 4; c++) {
        const int k0 = c * 512;
        for (int i = tid; i < NOUT * 512; i += 256) {
            int o = i >> 9, kk = i & 511;
            const float* Ap = Aps[o >> 3];
            sA[i] = Ap[(o & 7) * DMODEL + k0 + kk];
        }
        __syncthreads();
        const float* xr = X + (size_t)m * DMODEL + k0;
#pragma unroll 4
        for (int j = 0; j < 32; j++) {
            int kk = slice + j * 16;
            float xv = xr[kk];
#pragma unroll
            for (int o = 0; o < NOUT; o++) acc[o] += xv * sA[o * 512 + kk];
        }
        __syncthreads();
    }
#pragma unroll
    for (int o = 0; o < NOUT; o++) {
        float v = acc[o];
        v += __shfl_xor_sync(0xffffffffu, v, 1);
        v += __shfl_xor_sync(0xffffffffu, v, 2);
        v += __shfl_xor_sync(0xffffffffu, v, 4);
        v += __shfl_xor_sync(0xffffffffu, v, 8);
        if (slice == 0) T[(size_t)m * NOUT + o] = v;
    }
}

// ---------------------------------------------------------------------------
// mma.sync GEMM (fp16 TWO-product: Ahi*Bhi + Alo*Bhi = A * fp16(W)).
// 128x128 tile, 8 warps, K-block 64, two-stage cp.async, ldmatrix loads.
// MODE 0: single matrix, fp32 out. MODE 1: FUSED QKV (N=6144).
// ---------------------------------------------------------------------------
#define GKB        64
#define ROWB       144
#define MAT_BYTES  (128 * ROWB)          // 18432
#define STAGE_B    (3 * MAT_BYTES)       // 55296 (Ahi|Alo|Whi)
#define GEMM_SMEM  (2 * STAGE_B)         // 110592
#define NKITER     (DMODEL / GKB)        // 32

__device__ __forceinline__ void gemm_load_stage(
    uint32_t sbase, int tid, int s,
    const __half* gAh, const __half* gAl, const __half* gBh)
{
    const uint32_t base = sbase + (s & 1) * STAGE_B;
    const int kt = s * GKB;
    const __half* srcs[3] = {gAh, gAl, gBh};
#pragma unroll
    for (int mat = 0; mat < 3; mat++) {
        const __half* g = srcs[mat];
        uint32_t mbase = base + mat * MAT_BYTES;
#pragma unroll
        for (int t = 0; t < 4; t++) {
            int chunk = tid + t * 256;
            int row = chunk >> 3;
            int cc  = chunk & 7;
            cp16(mbase + row * ROWB + cc * 16,
                 g + (size_t)row * DMODEL + kt + cc * 8);
        }
    }
    CP_COMMIT();
}

template <int MODE>
__global__ void __launch_bounds__(256)
gemm_mma_kernel(const __half* __restrict__ Ahi, const __half* __restrict__ Alo,
                const __half* __restrict__ Bhi,
                const float* __restrict__ bias0, const float* __restrict__ bias1,
                const float* __restrict__ bias2,
                const float* __restrict__ T,
                const float* __restrict__ Bm0, const float* __restrict__ Bm1,
                const float* __restrict__ Bm2,
                float* __restrict__ YoutF,
                __half* __restrict__ YH0, __half* __restrict__ YL0,
                __half* __restrict__ YH1, __half* __restrict__ YL1,
                __half* __restrict__ YH2, __half* __restrict__ YL2,
                int tstride)
{
    extern __shared__ __align__(16) char smem[];
    uint32_t sbase = smem_u32(smem);
    const int tid  = threadIdx.x;
    const int wid  = tid >> 5;
    const int lane = tid & 31;
    const int g    = lane >> 2;
    const int t4   = lane & 3;
    const int wm   = (wid & 1) * 64;
    const int wn   = (wid >> 1) * 32;
    const int m0  = blockIdx.y * 128;
    const int n0g = blockIdx.x * 128;
    const int mat = (MODE == 1) ? (n0g >> 11) : 0;
    const int n0  = n0g & 2047;
    const int toff = (MODE == 1) ? mat * 8 : 0;

    const float* biasP = (mat == 0) ? bias0 : (mat == 1) ? bias1 : bias2;
    const float* BmP   = (mat == 0) ? Bm0   : (mat == 1) ? Bm1   : Bm2;
    __half* YH = (mat == 0) ? YH0 : (mat == 1) ? YH1 : YH2;
    __half* YL = (mat == 0) ? YL0 : (mat == 1) ? YL1 : YL2;

    const int lrow = lane & 7;
    const uint32_t aLane = (uint32_t)((wm + ((lane >> 3) & 1) * 8 + lrow) * ROWB + (lane >> 4) * 16);
    const uint32_t bLane = (uint32_t)((wn + ((lane >> 4) & 1) * 8 + lrow) * ROWB + ((lane >> 3) & 1) * 16);

    const __half* gAh = Ahi + (size_t)m0 * DMODEL;
    const __half* gAl = Alo + (size_t)m0 * DMODEL;
    const __half* gBh = Bhi + (size_t)n0g * DMODEL;

    float acc[4][4][4];
#pragma unroll
    for (int i = 0; i < 4; i++)
#pragma unroll
        for (int j = 0; j < 4; j++)
#pragma unroll
            for (int r = 0; r < 4; r++) acc[i][j][r] = 0.0f;

    gemm_load_stage(sbase, tid, 0, gAh, gAl, gBh);
    gemm_load_stage(sbase, tid, 1, gAh, gAl, gBh);

    for (int s = 0; s < NKITER; s++) {
        if (s == NKITER - 1) { CP_WAIT(0); } else { CP_WAIT(1); }
        __syncthreads();

        const uint32_t st = sbase + (s & 1) * STAGE_B;
        const uint32_t aHiA = st + aLane;
        const uint32_t aLoA = aHiA + MAT_BYTES;
        const uint32_t bHiA = st + 2 * MAT_BYTES + bLane;

#pragma unroll
        for (int kh = 0; kh < 4; kh++) {
            const uint32_t ko = kh * 32;
            uint32_t ah[4][4], al[4][4], bh[4][2];
#pragma unroll
            for (int mi = 0; mi < 4; mi++)
                LDSM_X4(ah[mi][0], ah[mi][1], ah[mi][2], ah[mi][3],
                        aHiA + mi * (16 * ROWB) + ko);
#pragma unroll
            for (int p = 0; p < 2; p++)
                LDSM_X4(bh[2 * p][0], bh[2 * p][1], bh[2 * p + 1][0], bh[2 * p + 1][1],
                        bHiA + p * (16 * ROWB) + ko);
#pragma unroll
            for (int mi = 0; mi < 4; mi++)
#pragma unroll
                for (int ni = 0; ni < 4; ni++)
                    MMA16816(acc[mi][ni], ah[mi], bh[ni]);

#pragma unroll
            for (int mi = 0; mi < 4; mi++)
                LDSM_X4(al[mi][0], al[mi][1], al[mi][2], al[mi][3],
                        aLoA + mi * (16 * ROWB) + ko);
#pragma unroll
            for (int mi = 0; mi < 4; mi++)
#pragma unroll
                for (int ni = 0; ni < 4; ni++)
                    MMA16816(acc[mi][ni], al[mi], bh[ni]);
        }

        __syncthreads();
        if (s + 2 < NKITER)
            gemm_load_stage(sbase, tid, s + 2, gAh, gAl, gBh);
    }

    // Epilogue
    __syncthreads();
    float* sT = (float*)smem;
    float* sB = (float*)(smem + 4096);
    {
        int row = tid >> 1;
        int half = tid & 1;
        float4 tv = *(const float4*)&T[(size_t)(m0 + row) * tstride + toff + half * 4];
        *(float4*)&sT[row * 8 + half * 4] = tv;
        float4 bv = *(const float4*)&BmP[(size_t)(n0 + row) * 8 + half * 4];
        *(float4*)&sB[row * 8 + half * 4] = bv;
    }
    __syncthreads();

#pragma unroll
    for (int mi = 0; mi < 4; mi++) {
        int rl0 = wm + mi * 16 + g;
#pragma unroll
        for (int rr = 0; rr < 2; rr++) {
            int rl = rl0 + rr * 8;
            int m = m0 + rl;
            const float* tr = &sT[rl * 8];
#pragma unroll
            for (int ni = 0; ni < 4; ni++) {
                int cl = wn + ni * 8 + t4 * 2;
                int n = n0 + cl;
                float d0 = acc[mi][ni][rr * 2 + 0];
                float d1 = acc[mi][ni][rr * 2 + 1];
                const float* b0 = &sB[cl * 8];
                const float* b1 = &sB[(cl + 1) * 8];
                float dot0 = 0.0f, dot1 = 0.0f;
#pragma unroll
                for (int r = 0; r < 8; r++) { dot0 += tr[r] * b0[r]; dot1 += tr[r] * b1[r]; }
                float yx = d0 + biasP[n]     + LORA_SCALING * dot0;
                float yy = d1 + biasP[n + 1] + LORA_SCALING * dot1;
                if (MODE == 0) {
                    *(float2*)&YoutF[(size_t)m * DMODEL + n] = make_float2(yx, yy);
                } else {
                    int bb = m >> 11, ss = m & 2047;
                    int h = n >> 7, d = n & 127;
                    size_t idx = ((((size_t)bb * NHEADS + h) * SEQ + ss) << 7) + d;
                    uint32_t hv, lv;
                    split2(yx, yy, hv, lv);
                    *(uint32_t*)&YH[idx] = hv;
                    *(uint32_t*)&YL[idx] = lv;
                }
            }
        }
    }
}

// ---------------------------------------------------------------------------
// V transpose: [bh][s][d] -> [bh][d][s], hi and lo.
// ---------------------------------------------------------------------------
__global__ void __launch_bounds__(256)
vtrans_kernel(const __half* __restrict__ vh, const __half* __restrict__ vl,
              __half* __restrict__ vth, __half* __restrict__ vtl)
{
    __shared__ __half tile[64][65];
    const int tid = threadIdx.x;
    const int bh = blockIdx.z;
    const int s0 = blockIdx.x * 64;
    const int d0 = blockIdx.y * 64;

    const __half* srcs[2] = {vh, vl};
    __half* dsts[2] = {vth, vtl};

#pragma unroll
    for (int pass = 0; pass < 2; pass++) {
        const __half* src = srcs[pass] + ((size_t)bh * SEQ + s0) * DK + d0;
        __half* dst = dsts[pass] + ((size_t)bh * DK + d0) * SEQ + s0;
        {
            int i = tid >> 2;
            int jp = tid & 3;
#pragma unroll
            for (int c = 0; c < 8; c++) {
                int j2 = jp * 8 + c;
                __half2 v = *(const __half2*)(src + (size_t)i * DK + j2 * 2);
                tile[i][j2 * 2] = __low2half(v);
                tile[i][j2 * 2 + 1] = __high2half(v);
            }
        }
        __syncthreads();
        {
            int r = tid >> 5;
            int wp = tid & 31;
#pragma unroll
            for (int p = 0; p < 8; p++) {
                int row = r + p * 8;
                __half2 v = __halves2half2(tile[2 * wp][row], tile[2 * wp + 1][row]);
                *(__half2*)(dst + (size_t)row * SEQ + 2 * wp) = v;
            }
        }
        __syncthreads();
    }
}

// ---------------------------------------------------------------------------
// Flash attention (fp16 hi/lo, 3 products, ldmatrix loads). fp32 ctx out.
// ---------------------------------------------------------------------------
#define FQROW  272
#define FQSZ   (128 * FQROW)
#define FQSZ2  (2 * FQSZ)
#define FKSZ   (64 * FQROW)
#define FVROW  144
#define FVSZ   (128 * FVROW)
#define FSTAGE (2 * FKSZ + 2 * FVSZ)
#define FLASH_SMEM (FQSZ2 + 2 * FSTAGE)  // 212992
#define NKVT   (SEQ / 64)

__device__ __forceinline__ void flash_load_stage(
    uint32_t sbase, int tid, int j,
    const __half* Kh, const __half* Kl,
    const __half* VTh, const __half* VTl)
{
    const uint32_t st = sbase + FQSZ2 + (j & 1) * FSTAGE;
    const int kv0 = j * 64;
#pragma unroll
    for (int w = 0; w < 4; w++) {
        int chunk = tid + w * 256;
        int row = chunk >> 4;
        int c   = chunk & 15;
        size_t go = (size_t)(kv0 + row) * DK + c * 8;
        cp16(st + row * FQROW + c * 16, Kh + go);
        cp16(st + FKSZ + row * FQROW + c * 16, Kl + go);
    }
#pragma unroll
    for (int w = 0; w < 4; w++) {
        int chunk = tid + w * 256;
        int row = chunk >> 3;
        int c   = chunk & 7;
        size_t go = (size_t)row * SEQ + kv0 + c * 8;
        cp16(st + 2 * FKSZ + row * FVROW + c * 16, VTh + go);
        cp16(st + 2 * FKSZ + FVSZ + row * FVROW + c * 16, VTl + go);
    }
    CP_COMMIT();
}

__global__ void __launch_bounds__(256)
flash_mma_kernel(const __half* __restrict__ Qhi, const __half* __restrict__ Qlo,
                 const __half* __restrict__ Khi, const __half* __restrict__ Klo,
                 const __half* __restrict__ VThi, const __half* __restrict__ VTlo,
                 float* __restrict__ CTX)
{
    extern __shared__ __align__(16) char smem[];
    uint32_t sbase = smem_u32(smem);
    const int tid  = threadIdx.x;
    const int wid  = tid >> 5;
    const int lane = tid & 31;
    const int g    = lane >> 2;
    const int t4   = lane & 3;
    const int wm   = wid * 16;
    const int bh = blockIdx.y;
    const int q0 = blockIdx.x * 128;

    const int lrow = lane & 7;
    const uint32_t qLane = (uint32_t)((wm + ((lane >> 3) & 1) * 8 + lrow) * FQROW + (lane >> 4) * 16);
    const uint32_t kLane = (uint32_t)((((lane >> 4) & 1) * 8 + lrow) * FQROW + ((lane >> 3) & 1) * 16);
    const uint32_t vLane = (uint32_t)((((lane >> 4) & 1) * 8 + lrow) * FVROW + ((lane >> 3) & 1) * 16);

    const __half* Qh = Qhi + ((size_t)bh * SEQ + q0) * DK;
    const __half* Ql = Qlo + ((size_t)bh * SEQ + q0) * DK;
    const __half* Kh = Khi + (size_t)bh * SEQ * DK;
    const __half* Kl = Klo + (size_t)bh * SEQ * DK;
    const __half* Vh = VThi + (size_t)bh * DK * SEQ;
    const __half* Vl = VTlo + (size_t)bh * DK * SEQ;

#pragma unroll
    for (int w = 0; w < 8; w++) {
        int chunk = tid + w * 256;
        int row = chunk >> 4;
        int c   = chunk & 15;
        size_t go = (size_t)row * DK + c * 8;
        cp16(sbase + row * FQROW + c * 16, Qh + go);
        cp16(sbase + FQSZ + row * FQROW + c * 16, Ql + go);
    }
    flash_load_stage(sbase, tid, 0, Kh, Kl, Vh, Vl);
    flash_load_stage(sbase, tid, 1, Kh, Kl, Vh, Vl);

    float m0 = -INFINITY, m1 = -INFINITY, l0 = 0.0f, l1 = 0.0f;
    float oacc[16][4];
#pragma unroll
    for (int i = 0; i < 16; i++)
#pragma unroll
        for (int r = 0; r < 4; r++) oacc[i][r] = 0.0f;

    for (int j = 0; j < NKVT; j++) {
        if (j == NKVT - 1) { CP_WAIT(0); } else { CP_WAIT(1); }
        __syncthreads();
        const uint32_t st = sbase + FQSZ2 + (j & 1) * FSTAGE;

        float sacc[8][4];
#pragma unroll
        for (int nb = 0; nb < 8; nb++)
#pragma unroll
            for (int r = 0; r < 4; r++) sacc[nb][r] = 0.0f;

#pragma unroll
        for (int kb = 0; kb < 8; kb++) {
            const uint32_t ko = kb * 32;
            uint32_t qh[4], ql[4];
            LDSM_X4(qh[0], qh[1], qh[2], qh[3], sbase + qLane + ko);
            LDSM_X4(ql[0], ql[1], ql[2], ql[3], sbase + FQSZ + qLane + ko);
#pragma unroll
            for (int p = 0; p < 4; p++) {
                uint32_t bhF[2][2], blF[2][2];
                uint32_t ka = st + kLane + p * (16 * FQROW) + ko;
                LDSM_X4(bhF[0][0], bhF[0][1], bhF[1][0], bhF[1][1], ka);
                LDSM_X4(blF[0][0], blF[0][1], blF[1][0], blF[1][1], ka + FKSZ);
#pragma unroll
                for (int q = 0; q < 2; q++) {
                    int nb = 2 * p + q;
                    MMA16816(sacc[nb], qh, bhF[q]);
                    MMA16816(sacc[nb], qh, blF[q]);
                    MMA16816(sacc[nb], ql, bhF[q]);
                }
            }
        }

        float mx0 = -INFINITY, mx1 = -INFINITY;
#pragma unroll
        for (int nb = 0; nb < 8; nb++) {
#pragma unroll
            for (int r = 0; r < 4; r++) sacc[nb][r] *= SM_SCALE;
            mx0 = fmaxf(mx0, fmaxf(sacc[nb][0], sacc[nb][1]));
            mx1 = fmaxf(mx1, fmaxf(sacc[nb][2], sacc[nb][3]));
        }
        mx0 = fmaxf(mx0, __shfl_xor_sync(0xffffffffu, mx0, 1));
        mx0 = fmaxf(mx0, __shfl_xor_sync(0xffffffffu, mx0, 2));
        mx1 = fmaxf(mx1, __shfl_xor_sync(0xffffffffu, mx1, 1));
        mx1 = fmaxf(mx1, __shfl_xor_sync(0xffffffffu, mx1, 2));

        float mn0 = fmaxf(m0, mx0), mn1 = fmaxf(m1, mx1);
        float sc0 = __expf(m0 - mn0), sc1 = __expf(m1 - mn1);
        m0 = mn0; m1 = mn1;

        float rs0 = 0.0f, rs1 = 0.0f;
#pragma unroll
        for (int nb = 0; nb < 8; nb++) {
            float p0 = __expf(sacc[nb][0] - mn0);
            float p1 = __expf(sacc[nb][1] - mn0);
            float p2 = __expf(sacc[nb][2] - mn1);
            float p3 = __expf(sacc[nb][3] - mn1);
            sacc[nb][0] = p0; sacc[nb][1] = p1; sacc[nb][2] = p2; sacc[nb][3] = p3;
            rs0 += p0 + p1; rs1 += p2 + p3;
        }
        rs0 += __shfl_xor_sync(0xffffffffu, rs0, 1);
        rs0 += __shfl_xor_sync(0xffffffffu, rs0, 2);
        rs1 += __shfl_xor_sync(0xffffffffu, rs1, 1);
        rs1 += __shfl_xor_sync(0xffffffffu, rs1, 2);
        l0 = l0 * sc0 + rs0;
        l1 = l1 * sc1 + rs1;

#pragma unroll
        for (int nb = 0; nb < 16; nb++) {
            oacc[nb][0] *= sc0; oacc[nb][1] *= sc0;
            oacc[nb][2] *= sc1; oacc[nb][3] *= sc1;
        }

        uint32_t ph[4][4], pl[4][4];
#pragma unroll
        for (int kb = 0; kb < 4; kb++) {
            split2(sacc[2 * kb][0],     sacc[2 * kb][1],     ph[kb][0], pl[kb][0]);
            split2(sacc[2 * kb][2],     sacc[2 * kb][3],     ph[kb][1], pl[kb][1]);
            split2(sacc[2 * kb + 1][0], sacc[2 * kb + 1][1], ph[kb][2], pl[kb][2]);
            split2(sacc[2 * kb + 1][2], sacc[2 * kb + 1][3], ph[kb][3], pl[kb][3]);
        }

        const uint32_t vb = st + 2 * FKSZ;
#pragma unroll
        for (int kb = 0; kb < 4; kb++) {
            const uint32_t ko = kb * 32;
#pragma unroll
            for (int p = 0; p < 8; p++) {
                uint32_t bhF[2][2], blF[2][2];
                uint32_t va = vb + vLane + p * (16 * FVROW) + ko;
                LDSM_X4(bhF[0][0], bhF[0][1], bhF[1][0], bhF[1][1], va);
                LDSM_X4(blF[0][0], blF[0][1], blF[1][0], blF[1][1], va + FVSZ);
#pragma unroll
                for (int q = 0; q < 2; q++) {
                    int nb = 2 * p + q;
                    MMA16816(oacc[nb], ph[kb], bhF[q]);
                    MMA16816(oacc[nb], ph[kb], blF[q]);
                    MMA16816(oacc[nb], pl[kb], bhF[q]);
                }
            }
        }

        __syncthreads();
        if (j + 2 < NKVT)
            flash_load_stage(sbase, tid, j + 2, Kh, Kl, Vh, Vl);
    }

    // write ctx fp32 token-major: [b*S+s][h*128+d]
    const int b = bh >> 4;
    const int h = bh & 15;
    const float inv0 = 1.0f / l0;
    const float inv1 = 1.0f / l1;
    const int s0r = q0 + wm + g;
    float* o0 = &CTX[((size_t)(b * SEQ + s0r)) * DMODEL + h * DK];
    float* o1 = &CTX[((size_t)(b * SEQ + s0r + 8)) * DMODEL + h * DK];
#pragma unroll
    for (int nb = 0; nb < 16; nb++) {
        int d = nb * 8 + t4 * 2;
        *(float2*)&o0[d] = make_float2(oacc[nb][0] * inv0, oacc[nb][1] * inv0);
        *(float2*)&o1[d] = make_float2(oacc[nb][2] * inv1, oacc[nb][3] * inv1);
    }
}

// ---------------------------------------------------------------------------
// Launch
// ---------------------------------------------------------------------------
extern "C" void kernel_launch(void* const* d_in, const int* in_sizes, int n_in,
                              void* d_out, int out_size)
{
    const float* x  = (const float*)d_in[0];
    const float* Wq = (const float*)d_in[1];
    const float* bq = (const float*)d_in[2];
    const float* Aq = (const float*)d_in[3];
    const float* Bq = (const float*)d_in[4];
    const float* Wk = (const float*)d_in[5];
    const float* bk = (const float*)d_in[6];
    const float* Ak = (const float*)d_in[7];
    const float* Bk = (const float*)d_in[8];
    const float* Wv = (const float*)d_in[9];
    const float* bv = (const float*)d_in[10];
    const float* Av = (const float*)d_in[11];
    const float* Bv = (const float*)d_in[12];
    const float* Wo = (const float*)d_in[13];
    const float* bo = (const float*)d_in[14];
    const float* Ao = (const float*)d_in[15];
    const float* Bo = (const float*)d_in[16];
    float* out = (float*)d_out;

    float *pt, *pto, *pctx;
    __half *pxhi, *pxlo, *pwhi, *pchi, *pclo;
    __half *pqhi, *pqlo, *pkhi, *pklo, *pvhi, *pvlo, *pvthi, *pvtlo;
    cudaGetSymbolAddress((void**)&pt,   g_t_qkv);
    cudaGetSymbolAddress((void**)&pto,  g_t_o);
    cudaGetSymbolAddress((void**)&pctx, g_ctx);
    cudaGetSymbolAddress((void**)&pxhi, g_xhi);
    cudaGetSymbolAddress((void**)&pxlo, g_xlo);
    cudaGetSymbolAddress((void**)&pwhi, g_whi);
    cudaGetSymbolAddress((void**)&pchi, g_chi);
    cudaGetSymbolAddress((void**)&pclo, g_clo);
    cudaGetSymbolAddress((void**)&pqhi, g_qhi);
    cudaGetSymbolAddress((void**)&pqlo, g_qlo);
    cudaGetSymbolAddress((void**)&pkhi, g_khi);
    cudaGetSymbolAddress((void**)&pklo, g_klo);
    cudaGetSymbolAddress((void**)&pvhi, g_vhi);
    cudaGetSymbolAddress((void**)&pvlo, g_vlo);
    cudaGetSymbolAddress((void**)&pvthi, g_vthi);
    cudaGetSymbolAddress((void**)&pvtlo, g_vtlo);

    cudaFuncSetAttribute(gemm_mma_kernel<0>,
                         cudaFuncAttributeMaxDynamicSharedMemorySize, GEMM_SMEM);
    cudaFuncSetAttribute(gemm_mma_kernel<1>,
                         cudaFuncAttributeMaxDynamicSharedMemorySize, GEMM_SMEM);
    cudaFuncSetAttribute(flash_mma_kernel,
                         cudaFuncAttributeMaxDynamicSharedMemorySize, FLASH_SMEM);

    const size_t WSZ = (size_t)DMODEL * DMODEL;
    const int nX4 = MTOT * DMODEL / 4;
    const int nW4 = (int)(WSZ / 4);
    const int sg  = 256;

    // 1) Splits (x hi/lo; weights hi only, Wq|Wk|Wv contiguous)
    split_kernel<<<(nX4 + sg - 1) / sg, sg>>>(x, pxhi, pxlo, nX4);
    split_hi_kernel<<<(nW4 + sg - 1) / sg, sg>>>(Wq, pwhi + 0 * WSZ, nW4);
    split_hi_kernel<<<(nW4 + sg - 1) / sg, sg>>>(Wk, pwhi + 1 * WSZ, nW4);
    split_hi_kernel<<<(nW4 + sg - 1) / sg, sg>>>(Wv, pwhi + 2 * WSZ, nW4);
    split_hi_kernel<<<(nW4 + sg - 1) / sg, sg>>>(Wo, pwhi + 3 * WSZ, nW4);

    // 2) LoRA intermediates (q|k|v)
    lora_kernel<24><<<MTOT / 16, 256>>>(x, Aq, Ak, Av, pt);

    // 3) FUSED QKV projection: one GEMM, N = 6144
    dim3 gQKV(3 * DMODEL / 128, MTOT / 128);   // (48, 32)
    gemm_mma_kernel<1><<<gQKV, 256, GEMM_SMEM>>>(
        pxhi, pxlo, pwhi,
        bq, bk, bv, pt, Bq, Bk, Bv,
        nullptr,
        pqhi, pqlo, pkhi, pklo, pvhi, pvlo, 24);

    // 4) V transpose
    dim3 tgrid(SEQ / 64, DK / 64, NBH);
    vtrans_kernel<<<tgrid, 256>>>(pvhi, pvlo, pvthi, pvtlo);

    // 5) Flash attention -> fp32 ctx
    dim3 fgrid(SEQ / 128, NBH);
    flash_mma_kernel<<<fgrid, 256, FLASH_SMEM>>>(pqhi, pqlo, pkhi, pklo, pvthi, pvtlo, pctx);

    // 6) Output projection
    split_kernel<<<(nX4 + sg - 1) / sg, sg>>>(pctx, pchi, pclo, nX4);
    lora_kernel<8><<<MTOT / 16, 256>>>(pctx, Ao, Ao, Ao, pto);
    dim3 gO(DMODEL / 128, MTOT / 128);         // (16, 32)
    gemm_mma_kernel<0><<<gO, 256, GEMM_SMEM>>>(
        pchi, pclo, pwhi + 3 * WSZ,
        bo, bo, bo, pto, Bo, Bo, Bo,
        out,
        nullptr, nullptr, nullptr, nullptr, nullptr, nullptr, 8);
}

// round 15
// speedup vs baseline: 1.2568x; 1.0270x over previous
#include <cuda_runtime.h>
#include <cuda_fp16.h>
#include <math.h>
#include <cstdint>

// Problem constants
#define BATCH     2
#define SEQ       2048
#define DMODEL    2048
#define NHEADS    16
#define DK        128
#define MTOT      (BATCH * SEQ)          // 4096
#define LORA_SCALING 2.0f
#define SM_SCALE  0.08838834764831845f   // 1/sqrt(128)
#define NBH       (BATCH * NHEADS)       // 32

// ---------------------------------------------------------------------------
// Scratch buffers (fp16 hi/lo)
// ---------------------------------------------------------------------------
#define HSZ (BATCH * NHEADS * SEQ * DK)  // 8388608
__device__ float g_t_qkv[MTOT * 24];
__device__ float g_t_o[MTOT * 8];
__device__ __half g_xhi[MTOT * DMODEL];
__device__ __half g_xlo[MTOT * DMODEL];
__device__ __half g_whi[4ull * DMODEL * DMODEL];   // hi only (2-product GEMM)
__device__ __half g_chi[MTOT * DMODEL];
__device__ __half g_clo[MTOT * DMODEL];
__device__ __half g_qhi[HSZ], g_qlo[HSZ];
__device__ __half g_khi[HSZ];                      // K: hi only (QK 2-product)
__device__ __half g_vhi[HSZ], g_vlo[HSZ];
__device__ __half g_vthi[HSZ], g_vtlo[HSZ];

// ---------------------------------------------------------------------------
// PTX helpers
// ---------------------------------------------------------------------------
__device__ __forceinline__ void cp16(uint32_t sm_dst, const void* g_src) {
    asm volatile("cp.async.cg.shared.global [%0], [%1], 16;" :: "r"(sm_dst), "l"(g_src) : "memory");
}
#define CP_COMMIT() asm volatile("cp.async.commit_group;" ::: "memory")
#define CP_WAIT(n)  asm volatile("cp.async.wait_group %0;" :: "n"(n) : "memory")

__device__ __forceinline__ uint32_t smem_u32(const void* p) {
    uint32_t a;
    asm("{ .reg .u64 t; cvta.to.shared.u64 t, %1; cvt.u32.u64 %0, t; }" : "=r"(a) : "l"(p));
    return a;
}
#define LDSM_X4(r0, r1, r2, r3, addr) \
    asm volatile("ldmatrix.sync.aligned.m8n8.x4.shared.b16 {%0,%1,%2,%3}, [%4];" \
        : "=r"(r0), "=r"(r1), "=r"(r2), "=r"(r3) : "r"(addr))

#define MMA16816(d, a, b) \
    asm volatile("mma.sync.aligned.m16n8k16.row.col.f32.f16.f16.f32 " \
        "{%0,%1,%2,%3}, {%4,%5,%6,%7}, {%8,%9}, {%0,%1,%2,%3};" \
        : "+f"((d)[0]), "+f"((d)[1]), "+f"((d)[2]), "+f"((d)[3]) \
        : "r"((a)[0]), "r"((a)[1]), "r"((a)[2]), "r"((a)[3]), \
          "r"((b)[0]), "r"((b)[1]))

__device__ __forceinline__ void split2(float a, float b, uint32_t& hi, uint32_t& lo) {
    __half ha = __float2half_rn(a), hb = __float2half_rn(b);
    __half la = __float2half_rn(a - __half2float(ha));
    __half lb = __float2half_rn(b - __half2float(hb));
    __half2 H = __halves2half2(ha, hb), L = __halves2half2(la, lb);
    hi = *(uint32_t*)&H;
    lo = *(uint32_t*)&L;
}

// ---------------------------------------------------------------------------
// fp32 -> fp16 hi/lo split
// ---------------------------------------------------------------------------
__global__ void __launch_bounds__(256)
split_kernel(const float* __restrict__ src, __half* __restrict__ hi,
             __half* __restrict__ lo, int n4)
{
    int i = blockIdx.x * 256 + threadIdx.x;
    if (i >= n4) return;
    float4 v = ((const float4*)src)[i];
    uint32_t h0, l0, h1, l1;
    split2(v.x, v.y, h0, l0);
    split2(v.z, v.w, h1, l1);
    uint32_t* hp = (uint32_t*)(hi + (size_t)i * 4);
    uint32_t* lp = (uint32_t*)(lo + (size_t)i * 4);
    hp[0] = h0; hp[1] = h1;
    lp[0] = l0; lp[1] = l1;
}

// fp32 -> fp16 (hi only, for weights)
__global__ void __launch_bounds__(256)
split_hi_kernel(const float* __restrict__ src, __half* __restrict__ hi, int n4)
{
    int i = blockIdx.x * 256 + threadIdx.x;
    if (i >= n4) return;
    float4 v = ((const float4*)src)[i];
    __half2 a = __halves2half2(__float2half_rn(v.x), __float2half_rn(v.y));
    __half2 b = __halves2half2(__float2half_rn(v.z), __float2half_rn(v.w));
    uint32_t* hp = (uint32_t*)(hi + (size_t)i * 4);
    hp[0] = *(uint32_t*)&a;
    hp[1] = *(uint32_t*)&b;
}

// ---------------------------------------------------------------------------
// LoRA intermediate T[m][o] = sum_k X[m][k] * A_(o/8)[o%8][k]  (fp32 X)
// ---------------------------------------------------------------------------
template <int NOUT>
__global__ void __launch_bounds__(256)
lora_kernel(const float* __restrict__ X,
            const float* __restrict__ A0, const float* __restrict__ A1,
            const float* __restrict__ A2, float* __restrict__ T)
{
    __shared__ float sA[NOUT * 512];
    const int tid   = threadIdx.x;
    const int row   = tid >> 4;
    const int slice = tid & 15;
    const int m     = blockIdx.x * 16 + row;
    const float* Aps[3] = {A0, A1, A2};

    float acc[NOUT];
#pragma unroll
    for (int o = 0; o < NOUT; o++) acc[o] = 0.0f;

    for (int c = 0; c < 4; c++) {
        const int k0 = c * 512;
        for (int i = tid; i < NOUT * 512; i += 256) {
            int o = i >> 9, kk = i & 511;
            const float* Ap = Aps[o >> 3];
            sA[i] = Ap[(o & 7) * DMODEL + k0 + kk];
        }
        __syncthreads();
        const float* xr = X + (size_t)m * DMODEL + k0;
#pragma unroll 4
        for (int j = 0; j < 32; j++) {
            int kk = slice + j * 16;
            float xv = xr[kk];
#pragma unroll
            for (int o = 0; o < NOUT; o++) acc[o] += xv * sA[o * 512 + kk];
        }
        __syncthreads();
    }
#pragma unroll
    for (int o = 0; o < NOUT; o++) {
        float v = acc[o];
        v += __shfl_xor_sync(0xffffffffu, v, 1);
        v += __shfl_xor_sync(0xffffffffu, v, 2);
        v += __shfl_xor_sync(0xffffffffu, v, 4);
        v += __shfl_xor_sync(0xffffffffu, v, 8);
        if (slice == 0) T[(size_t)m * NOUT + o] = v;
    }
}

// fp16 hi/lo input variant (for ctx)
template <int NOUT>
__global__ void __launch_bounds__(256)
lora_h_kernel(const __half* __restrict__ XH, const __half* __restrict__ XL,
              const float* __restrict__ A0, float* __restrict__ T)
{
    __shared__ float sA[NOUT * 512];
    const int tid   = threadIdx.x;
    const int row   = tid >> 4;
    const int slice = tid & 15;
    const int m     = blockIdx.x * 16 + row;

    float acc[NOUT];
#pragma unroll
    for (int o = 0; o < NOUT; o++) acc[o] = 0.0f;

    for (int c = 0; c < 4; c++) {
        const int k0 = c * 512;
        for (int i = tid; i < NOUT * 512; i += 256) {
            int o = i >> 9, kk = i & 511;
            sA[i] = A0[o * DMODEL + k0 + kk];
        }
        __syncthreads();
        const __half* xh = XH + (size_t)m * DMODEL + k0;
        const __half* xl = XL + (size_t)m * DMODEL + k0;
#pragma unroll 4
        for (int j = 0; j < 32; j++) {
            int kk = slice + j * 16;
            float xv = __half2float(xh[kk]) + __half2float(xl[kk]);
#pragma unroll
            for (int o = 0; o < NOUT; o++) acc[o] += xv * sA[o * 512 + kk];
        }
        __syncthreads();
    }
#pragma unroll
    for (int o = 0; o < NOUT; o++) {
        float v = acc[o];
        v += __shfl_xor_sync(0xffffffffu, v, 1);
        v += __shfl_xor_sync(0xffffffffu, v, 2);
        v += __shfl_xor_sync(0xffffffffu, v, 4);
        v += __shfl_xor_sync(0xffffffffu, v, 8);
        if (slice == 0) T[(size_t)m * NOUT + o] = v;
    }
}

// ---------------------------------------------------------------------------
// mma.sync GEMM (fp16 two-product). 128x128 tile, 8 warps, K-block 64,
// two-stage cp.async, ldmatrix loads.
// MODE 0: single matrix, fp32 out. MODE 1: FUSED QKV (N=6144; K writes hi only).
// ---------------------------------------------------------------------------
#define GKB        64
#define ROWB       144
#define MAT_BYTES  (128 * ROWB)          // 18432
#define STAGE_B    (3 * MAT_BYTES)       // 55296 (Ahi|Alo|Whi)
#define GEMM_SMEM  (2 * STAGE_B)         // 110592
#define NKITER     (DMODEL / GKB)        // 32

__device__ __forceinline__ void gemm_load_stage(
    uint32_t sbase, int tid, int s,
    const __half* gAh, const __half* gAl, const __half* gBh)
{
    const uint32_t base = sbase + (s & 1) * STAGE_B;
    const int kt = s * GKB;
    const __half* srcs[3] = {gAh, gAl, gBh};
#pragma unroll
    for (int mat = 0; mat < 3; mat++) {
        const __half* g = srcs[mat];
        uint32_t mbase = base + mat * MAT_BYTES;
#pragma unroll
        for (int t = 0; t < 4; t++) {
            int chunk = tid + t * 256;
            int row = chunk >> 3;
            int cc  = chunk & 7;
            cp16(mbase + row * ROWB + cc * 16,
                 g + (size_t)row * DMODEL + kt + cc * 8);
        }
    }
    CP_COMMIT();
}

template <int MODE>
__global__ void __launch_bounds__(256)
gemm_mma_kernel(const __half* __restrict__ Ahi, const __half* __restrict__ Alo,
                const __half* __restrict__ Bhi,
                const float* __restrict__ bias0, const float* __restrict__ bias1,
                const float* __restrict__ bias2,
                const float* __restrict__ T,
                const float* __restrict__ Bm0, const float* __restrict__ Bm1,
                const float* __restrict__ Bm2,
                float* __restrict__ YoutF,
                __half* __restrict__ YH0, __half* __restrict__ YL0,
                __half* __restrict__ YH1, __half* __restrict__ YL1,
                __half* __restrict__ YH2, __half* __restrict__ YL2,
                int tstride)
{
    extern __shared__ __align__(16) char smem[];
    uint32_t sbase = smem_u32(smem);
    const int tid  = threadIdx.x;
    const int wid  = tid >> 5;
    const int lane = tid & 31;
    const int g    = lane >> 2;
    const int t4   = lane & 3;
    const int wm   = (wid & 1) * 64;
    const int wn   = (wid >> 1) * 32;
    const int m0  = blockIdx.y * 128;
    const int n0g = blockIdx.x * 128;
    const int mat = (MODE == 1) ? (n0g >> 11) : 0;
    const int n0  = n0g & 2047;
    const int toff = (MODE == 1) ? mat * 8 : 0;

    const float* biasP = (mat == 0) ? bias0 : (mat == 1) ? bias1 : bias2;
    const float* BmP   = (mat == 0) ? Bm0   : (mat == 1) ? Bm1   : Bm2;
    __half* YH = (mat == 0) ? YH0 : (mat == 1) ? YH1 : YH2;
    __half* YL = (mat == 0) ? YL0 : (mat == 1) ? YL1 : YL2;

    const int lrow = lane & 7;
    const uint32_t aLane = (uint32_t)((wm + ((lane >> 3) & 1) * 8 + lrow) * ROWB + (lane >> 4) * 16);
    const uint32_t bLane = (uint32_t)((wn + ((lane >> 4) & 1) * 8 + lrow) * ROWB + ((lane >> 3) & 1) * 16);

    const __half* gAh = Ahi + (size_t)m0 * DMODEL;
    const __half* gAl = Alo + (size_t)m0 * DMODEL;
    const __half* gBh = Bhi + (size_t)n0g * DMODEL;

    float acc[4][4][4];
#pragma unroll
    for (int i = 0; i < 4; i++)
#pragma unroll
        for (int j = 0; j < 4; j++)
#pragma unroll
            for (int r = 0; r < 4; r++) acc[i][j][r] = 0.0f;

    gemm_load_stage(sbase, tid, 0, gAh, gAl, gBh);
    gemm_load_stage(sbase, tid, 1, gAh, gAl, gBh);

    for (int s = 0; s < NKITER; s++) {
        if (s == NKITER - 1) { CP_WAIT(0); } else { CP_WAIT(1); }
        __syncthreads();

        const uint32_t st = sbase + (s & 1) * STAGE_B;
        const uint32_t aHiA = st + aLane;
        const uint32_t aLoA = aHiA + MAT_BYTES;
        const uint32_t bHiA = st + 2 * MAT_BYTES + bLane;

#pragma unroll
        for (int kh = 0; kh < 4; kh++) {
            const uint32_t ko = kh * 32;
            uint32_t ah[4][4], al[4][4], bh[4][2];
#pragma unroll
            for (int mi = 0; mi < 4; mi++)
                LDSM_X4(ah[mi][0], ah[mi][1], ah[mi][2], ah[mi][3],
                        aHiA + mi * (16 * ROWB) + ko);
#pragma unroll
            for (int p = 0; p < 2; p++)
                LDSM_X4(bh[2 * p][0], bh[2 * p][1], bh[2 * p + 1][0], bh[2 * p + 1][1],
                        bHiA + p * (16 * ROWB) + ko);
#pragma unroll
            for (int mi = 0; mi < 4; mi++)
#pragma unroll
                for (int ni = 0; ni < 4; ni++)
                    MMA16816(acc[mi][ni], ah[mi], bh[ni]);

#pragma unroll
            for (int mi = 0; mi < 4; mi++)
                LDSM_X4(al[mi][0], al[mi][1], al[mi][2], al[mi][3],
                        aLoA + mi * (16 * ROWB) + ko);
#pragma unroll
            for (int mi = 0; mi < 4; mi++)
#pragma unroll
                for (int ni = 0; ni < 4; ni++)
                    MMA16816(acc[mi][ni], al[mi], bh[ni]);
        }

        __syncthreads();
        if (s + 2 < NKITER)
            gemm_load_stage(sbase, tid, s + 2, gAh, gAl, gBh);
    }

    // Epilogue
    __syncthreads();
    float* sT = (float*)smem;
    float* sB = (float*)(smem + 4096);
    {
        int row = tid >> 1;
        int half = tid & 1;
        float4 tv = *(const float4*)&T[(size_t)(m0 + row) * tstride + toff + half * 4];
        *(float4*)&sT[row * 8 + half * 4] = tv;
        float4 bv = *(const float4*)&BmP[(size_t)(n0 + row) * 8 + half * 4];
        *(float4*)&sB[row * 8 + half * 4] = bv;
    }
    __syncthreads();

    const bool wantLo = (MODE == 0) || (YL != nullptr);
#pragma unroll
    for (int mi = 0; mi < 4; mi++) {
        int rl0 = wm + mi * 16 + g;
#pragma unroll
        for (int rr = 0; rr < 2; rr++) {
            int rl = rl0 + rr * 8;
            int m = m0 + rl;
            const float* tr = &sT[rl * 8];
#pragma unroll
            for (int ni = 0; ni < 4; ni++) {
                int cl = wn + ni * 8 + t4 * 2;
                int n = n0 + cl;
                float d0 = acc[mi][ni][rr * 2 + 0];
                float d1 = acc[mi][ni][rr * 2 + 1];
                const float* b0 = &sB[cl * 8];
                const float* b1 = &sB[(cl + 1) * 8];
                float dot0 = 0.0f, dot1 = 0.0f;
#pragma unroll
                for (int r = 0; r < 8; r++) { dot0 += tr[r] * b0[r]; dot1 += tr[r] * b1[r]; }
                float yx = d0 + biasP[n]     + LORA_SCALING * dot0;
                float yy = d1 + biasP[n + 1] + LORA_SCALING * dot1;
                if (MODE == 0) {
                    *(float2*)&YoutF[(size_t)m * DMODEL + n] = make_float2(yx, yy);
                } else {
                    int bb = m >> 11, ss = m & 2047;
                    int h = n >> 7, d = n & 127;
                    size_t idx = ((((size_t)bb * NHEADS + h) * SEQ + ss) << 7) + d;
                    uint32_t hv, lv;
                    split2(yx, yy, hv, lv);
                    *(uint32_t*)&YH[idx] = hv;
                    if (wantLo) *(uint32_t*)&YL[idx] = lv;
                }
            }
        }
    }
}

// ---------------------------------------------------------------------------
// V transpose: [bh][s][d] -> [bh][d][s], hi and lo.
// ---------------------------------------------------------------------------
__global__ void __launch_bounds__(256)
vtrans_kernel(const __half* __restrict__ vh, const __half* __restrict__ vl,
              __half* __restrict__ vth, __half* __restrict__ vtl)
{
    __shared__ __half tile[64][65];
    const int tid = threadIdx.x;
    const int bh = blockIdx.z;
    const int s0 = blockIdx.x * 64;
    const int d0 = blockIdx.y * 64;

    const __half* srcs[2] = {vh, vl};
    __half* dsts[2] = {vth, vtl};

#pragma unroll
    for (int pass = 0; pass < 2; pass++) {
        const __half* src = srcs[pass] + ((size_t)bh * SEQ + s0) * DK + d0;
        __half* dst = dsts[pass] + ((size_t)bh * DK + d0) * SEQ + s0;
        {
            int i = tid >> 2;
            int jp = tid & 3;
#pragma unroll
            for (int c = 0; c < 8; c++) {
                int j2 = jp * 8 + c;
                __half2 v = *(const __half2*)(src + (size_t)i * DK + j2 * 2);
                tile[i][j2 * 2] = __low2half(v);
                tile[i][j2 * 2 + 1] = __high2half(v);
            }
        }
        __syncthreads();
        {
            int r = tid >> 5;
            int wp = tid & 31;
#pragma unroll
            for (int p = 0; p < 8; p++) {
                int row = r + p * 8;
                __half2 v = __halves2half2(tile[2 * wp][row], tile[2 * wp + 1][row]);
                *(__half2*)(dst + (size_t)row * SEQ + 2 * wp) = v;
            }
        }
        __syncthreads();
    }
}

// ---------------------------------------------------------------------------
// Flash attention: QK 2-product (K hi only), PV 3-product, ldmatrix loads.
// Writes ctx as fp16 hi/lo directly.
// ---------------------------------------------------------------------------
#define FQROW  272
#define FQSZ   (128 * FQROW)
#define FQSZ2  (2 * FQSZ)
#define FKSZ   (64 * FQROW)              // K hi only
#define FVROW  144
#define FVSZ   (128 * FVROW)
#define FSTAGE (FKSZ + 2 * FVSZ)         // 54272
#define FLASH_SMEM (FQSZ2 + 2 * FSTAGE)  // 178176
#define NKVT   (SEQ / 64)

__device__ __forceinline__ void flash_load_stage(
    uint32_t sbase, int tid, int j,
    const __half* Kh, const __half* VTh, const __half* VTl)
{
    const uint32_t st = sbase + FQSZ2 + (j & 1) * FSTAGE;
    const int kv0 = j * 64;
#pragma unroll
    for (int w = 0; w < 4; w++) {            // K hi: 64 rows x 16 chunks
        int chunk = tid + w * 256;
        int row = chunk >> 4;
        int c   = chunk & 15;
        cp16(st + row * FQROW + c * 16,
             Kh + (size_t)(kv0 + row) * DK + c * 8);
    }
#pragma unroll
    for (int w = 0; w < 4; w++) {            // VT hi+lo: 128 rows x 8 chunks
        int chunk = tid + w * 256;
        int row = chunk >> 3;
        int c   = chunk & 7;
        size_t go = (size_t)row * SEQ + kv0 + c * 8;
        cp16(st + FKSZ + row * FVROW + c * 16, VTh + go);
        cp16(st + FKSZ + FVSZ + row * FVROW + c * 16, VTl + go);
    }
    CP_COMMIT();
}

__global__ void __launch_bounds__(256)
flash_mma_kernel(const __half* __restrict__ Qhi, const __half* __restrict__ Qlo,
                 const __half* __restrict__ Khi,
                 const __half* __restrict__ VThi, const __half* __restrict__ VTlo,
                 __half* __restrict__ CH, __half* __restrict__ CL)
{
    extern __shared__ __align__(16) char smem[];
    uint32_t sbase = smem_u32(smem);
    const int tid  = threadIdx.x;
    const int wid  = tid >> 5;
    const int lane = tid & 31;
    const int g    = lane >> 2;
    const int t4   = lane & 3;
    const int wm   = wid * 16;
    const int bh = blockIdx.y;
    const int q0 = blockIdx.x * 128;

    const int lrow = lane & 7;
    const uint32_t qLane = (uint32_t)((wm + ((lane >> 3) & 1) * 8 + lrow) * FQROW + (lane >> 4) * 16);
    const uint32_t kLane = (uint32_t)((((lane >> 4) & 1) * 8 + lrow) * FQROW + ((lane >> 3) & 1) * 16);
    const uint32_t vLane = (uint32_t)((((lane >> 4) & 1) * 8 + lrow) * FVROW + ((lane >> 3) & 1) * 16);

    const __half* Qh = Qhi + ((size_t)bh * SEQ + q0) * DK;
    const __half* Ql = Qlo + ((size_t)bh * SEQ + q0) * DK;
    const __half* Kh = Khi + (size_t)bh * SEQ * DK;
    const __half* Vh = VThi + (size_t)bh * DK * SEQ;
    const __half* Vl = VTlo + (size_t)bh * DK * SEQ;

#pragma unroll
    for (int w = 0; w < 8; w++) {
        int chunk = tid + w * 256;
        int row = chunk >> 4;
        int c   = chunk & 15;
        size_t go = (size_t)row * DK + c * 8;
        cp16(sbase + row * FQROW + c * 16, Qh + go);
        cp16(sbase + FQSZ + row * FQROW + c * 16, Ql + go);
    }
    flash_load_stage(sbase, tid, 0, Kh, Vh, Vl);
    flash_load_stage(sbase, tid, 1, Kh, Vh, Vl);

    float m0 = -INFINITY, m1 = -INFINITY, l0 = 0.0f, l1 = 0.0f;
    float oacc[16][4];
#pragma unroll
    for (int i = 0; i < 16; i++)
#pragma unroll
        for (int r = 0; r < 4; r++) oacc[i][r] = 0.0f;

    for (int j = 0; j < NKVT; j++) {
        if (j == NKVT - 1) { CP_WAIT(0); } else { CP_WAIT(1); }
        __syncthreads();
        const uint32_t st = sbase + FQSZ2 + (j & 1) * FSTAGE;

        float sacc[8][4];
#pragma unroll
        for (int nb = 0; nb < 8; nb++)
#pragma unroll
            for (int r = 0; r < 4; r++) sacc[nb][r] = 0.0f;

        // ---- QK (2 products: (qh+ql) * fp16(K)) ----
#pragma unroll
        for (int kb = 0; kb < 8; kb++) {
            const uint32_t ko = kb * 32;
            uint32_t qh[4], ql[4];
            LDSM_X4(qh[0], qh[1], qh[2], qh[3], sbase + qLane + ko);
            LDSM_X4(ql[0], ql[1], ql[2], ql[3], sbase + FQSZ + qLane + ko);
#pragma unroll
            for (int p = 0; p < 4; p++) {
                uint32_t bhF[2][2];
                uint32_t ka = st + kLane + p * (16 * FQROW) + ko;
                LDSM_X4(bhF[0][0], bhF[0][1], bhF[1][0], bhF[1][1], ka);
#pragma unroll
                for (int q = 0; q < 2; q++) {
                    int nb = 2 * p + q;
                    MMA16816(sacc[nb], qh, bhF[q]);
                    MMA16816(sacc[nb], ql, bhF[q]);
                }
            }
        }

        float mx0 = -INFINITY, mx1 = -INFINITY;
#pragma unroll
        for (int nb = 0; nb < 8; nb++) {
#pragma unroll
            for (int r = 0; r < 4; r++) sacc[nb][r] *= SM_SCALE;
            mx0 = fmaxf(mx0, fmaxf(sacc[nb][0], sacc[nb][1]));
            mx1 = fmaxf(mx1, fmaxf(sacc[nb][2], sacc[nb][3]));
        }
        mx0 = fmaxf(mx0, __shfl_xor_sync(0xffffffffu, mx0, 1));
        mx0 = fmaxf(mx0, __shfl_xor_sync(0xffffffffu, mx0, 2));
        mx1 = fmaxf(mx1, __shfl_xor_sync(0xffffffffu, mx1, 1));
        mx1 = fmaxf(mx1, __shfl_xor_sync(0xffffffffu, mx1, 2));

        float mn0 = fmaxf(m0, mx0), mn1 = fmaxf(m1, mx1);
        float sc0 = __expf(m0 - mn0), sc1 = __expf(m1 - mn1);
        m0 = mn0; m1 = mn1;

        float rs0 = 0.0f, rs1 = 0.0f;
#pragma unroll
        for (int nb = 0; nb < 8; nb++) {
            float p0 = __expf(sacc[nb][0] - mn0);
            float p1 = __expf(sacc[nb][1] - mn0);
            float p2 = __expf(sacc[nb][2] - mn1);
            float p3 = __expf(sacc[nb][3] - mn1);
            sacc[nb][0] = p0; sacc[nb][1] = p1; sacc[nb][2] = p2; sacc[nb][3] = p3;
            rs0 += p0 + p1; rs1 += p2 + p3;
        }
        rs0 += __shfl_xor_sync(0xffffffffu, rs0, 1);
        rs0 += __shfl_xor_sync(0xffffffffu, rs0, 2);
        rs1 += __shfl_xor_sync(0xffffffffu, rs1, 1);
        rs1 += __shfl_xor_sync(0xffffffffu, rs1, 2);
        l0 = l0 * sc0 + rs0;
        l1 = l1 * sc1 + rs1;

#pragma unroll
        for (int nb = 0; nb < 16; nb++) {
            oacc[nb][0] *= sc0; oacc[nb][1] *= sc0;
            oacc[nb][2] *= sc1; oacc[nb][3] *= sc1;
        }

        uint32_t ph[4][4], pl[4][4];
#pragma unroll
        for (int kb = 0; kb < 4; kb++) {
            split2(sacc[2 * kb][0],     sacc[2 * kb][1],     ph[kb][0], pl[kb][0]);
            split2(sacc[2 * kb][2],     sacc[2 * kb][3],     ph[kb][1], pl[kb][1]);
            split2(sacc[2 * kb + 1][0], sacc[2 * kb + 1][1], ph[kb][2], pl[kb][2]);
            split2(sacc[2 * kb + 1][2], sacc[2 * kb + 1][3], ph[kb][3], pl[kb][3]);
        }

        // ---- PV (3 products) ----
        const uint32_t vb = st + FKSZ;
#pragma unroll
        for (int kb = 0; kb < 4; kb++) {
            const uint32_t ko = kb * 32;
#pragma unroll
            for (int p = 0; p < 8; p++) {
                uint32_t bhF[2][2], blF[2][2];
                uint32_t va = vb + vLane + p * (16 * FVROW) + ko;
                LDSM_X4(bhF[0][0], bhF[0][1], bhF[1][0], bhF[1][1], va);
                LDSM_X4(blF[0][0], blF[0][1], blF[1][0], blF[1][1], va + FVSZ);
#pragma unroll
                for (int q = 0; q < 2; q++) {
                    int nb = 2 * p + q;
                    MMA16816(oacc[nb], ph[kb], bhF[q]);
                    MMA16816(oacc[nb], ph[kb], blF[q]);
                    MMA16816(oacc[nb], pl[kb], bhF[q]);
                }
            }
        }

        __syncthreads();
        if (j + 2 < NKVT)
            flash_load_stage(sbase, tid, j + 2, Kh, Vh, Vl);
    }

    // write ctx fp16 hi/lo token-major: [b*S+s][h*128+d]
    const int b = bh >> 4;
    const int h = bh & 15;
    const float inv0 = 1.0f / l0;
    const float inv1 = 1.0f / l1;
    const int s0r = q0 + wm + g;
    size_t idx0 = ((size_t)(b * SEQ + s0r)) * DMODEL + h * DK;
    size_t idx1 = ((size_t)(b * SEQ + s0r + 8)) * DMODEL + h * DK;
#pragma unroll
    for (int nb = 0; nb < 16; nb++) {
        int d = nb * 8 + t4 * 2;
        uint32_t hv, lv;
        split2(oacc[nb][0] * inv0, oacc[nb][1] * inv0, hv, lv);
        *(uint32_t*)&CH[idx0 + d] = hv;
        *(uint32_t*)&CL[idx0 + d] = lv;
        split2(oacc[nb][2] * inv1, oacc[nb][3] * inv1, hv, lv);
        *(uint32_t*)&CH[idx1 + d] = hv;
        *(uint32_t*)&CL[idx1 + d] = lv;
    }
}

// ---------------------------------------------------------------------------
// Launch
// ---------------------------------------------------------------------------
extern "C" void kernel_launch(void* const* d_in, const int* in_sizes, int n_in,
                              void* d_out, int out_size)
{
    const float* x  = (const float*)d_in[0];
    const float* Wq = (const float*)d_in[1];
    const float* bq = (const float*)d_in[2];
    const float* Aq = (const float*)d_in[3];
    const float* Bq = (const float*)d_in[4];
    const float* Wk = (const float*)d_in[5];
    const float* bk = (const float*)d_in[6];
    const float* Ak = (const float*)d_in[7];
    const float* Bk = (const float*)d_in[8];
    const float* Wv = (const float*)d_in[9];
    const float* bv = (const float*)d_in[10];
    const float* Av = (const float*)d_in[11];
    const float* Bv = (const float*)d_in[12];
    const float* Wo = (const float*)d_in[13];
    const float* bo = (const float*)d_in[14];
    const float* Ao = (const float*)d_in[15];
    const float* Bo = (const float*)d_in[16];
    float* out = (float*)d_out;

    float *pt, *pto;
    __half *pxhi, *pxlo, *pwhi, *pchi, *pclo;
    __half *pqhi, *pqlo, *pkhi, *pvhi, *pvlo, *pvthi, *pvtlo;
    cudaGetSymbolAddress((void**)&pt,   g_t_qkv);
    cudaGetSymbolAddress((void**)&pto,  g_t_o);
    cudaGetSymbolAddress((void**)&pxhi, g_xhi);
    cudaGetSymbolAddress((void**)&pxlo, g_xlo);
    cudaGetSymbolAddress((void**)&pwhi, g_whi);
    cudaGetSymbolAddress((void**)&pchi, g_chi);
    cudaGetSymbolAddress((void**)&pclo, g_clo);
    cudaGetSymbolAddress((void**)&pqhi, g_qhi);
    cudaGetSymbolAddress((void**)&pqlo, g_qlo);
    cudaGetSymbolAddress((void**)&pkhi, g_khi);
    cudaGetSymbolAddress((void**)&pvhi, g_vhi);
    cudaGetSymbolAddress((void**)&pvlo, g_vlo);
    cudaGetSymbolAddress((void**)&pvthi, g_vthi);
    cudaGetSymbolAddress((void**)&pvtlo, g_vtlo);

    cudaFuncSetAttribute(gemm_mma_kernel<0>,
                         cudaFuncAttributeMaxDynamicSharedMemorySize, GEMM_SMEM);
    cudaFuncSetAttribute(gemm_mma_kernel<1>,
                         cudaFuncAttributeMaxDynamicSharedMemorySize, GEMM_SMEM);
    cudaFuncSetAttribute(flash_mma_kernel,
                         cudaFuncAttributeMaxDynamicSharedMemorySize, FLASH_SMEM);

    const size_t WSZ = (size_t)DMODEL * DMODEL;
    const int nX4 = MTOT * DMODEL / 4;
    const int nW4 = (int)(WSZ / 4);
    const int sg  = 256;

    // 1) Splits (x hi/lo; weights hi only)
    split_kernel<<<(nX4 + sg - 1) / sg, sg>>>(x, pxhi, pxlo, nX4);
    split_hi_kernel<<<(nW4 + sg - 1) / sg, sg>>>(Wq, pwhi + 0 * WSZ, nW4);
    split_hi_kernel<<<(nW4 + sg - 1) / sg, sg>>>(Wk, pwhi + 1 * WSZ, nW4);
    split_hi_kernel<<<(nW4 + sg - 1) / sg, sg>>>(Wv, pwhi + 2 * WSZ, nW4);
    split_hi_kernel<<<(nW4 + sg - 1) / sg, sg>>>(Wo, pwhi + 3 * WSZ, nW4);

    // 2) LoRA intermediates (q|k|v)
    lora_kernel<24><<<MTOT / 16, 256>>>(x, Aq, Ak, Av, pt);

    // 3) FUSED QKV projection (K writes hi only)
    dim3 gQKV(3 * DMODEL / 128, MTOT / 128);   // (48, 32)
    gemm_mma_kernel<1><<<gQKV, 256, GEMM_SMEM>>>(
        pxhi, pxlo, pwhi,
        bq, bk, bv, pt, Bq, Bk, Bv,
        nullptr,
        pqhi, pqlo, pkhi, nullptr, pvhi, pvlo, 24);

    // 4) V transpose
    dim3 tgrid(SEQ / 64, DK / 64, NBH);
    vtrans_kernel<<<tgrid, 256>>>(pvhi, pvlo, pvthi, pvtlo);

    // 5) Flash attention -> ctx fp16 hi/lo
    dim3 fgrid(SEQ / 128, NBH);
    flash_mma_kernel<<<fgrid, 256, FLASH_SMEM>>>(pqhi, pqlo, pkhi, pvthi, pvtlo,
                                                 pchi, pclo);

    // 6) Output projection (ctx consumed directly as fp16 hi/lo)
    lora_h_kernel<8><<<MTOT / 16, 256>>>(pchi, pclo, Ao, pto);
    dim3 gO(DMODEL / 128, MTOT / 128);         // (16, 32)
    gemm_mma_kernel<0><<<gO, 256, GEMM_SMEM>>>(
        pchi, pclo, pwhi + 3 * WSZ,
        bo, bo, bo, pto, Bo, Bo, Bo,
        out,
        nullptr, nullptr, nullptr, nullptr, nullptr, nullptr, 8);
}

// round 16
// speedup vs baseline: 1.2588x; 1.0015x over previous
#include <cuda_runtime.h>
#include <cuda_fp16.h>
#include <math.h>
#include <cstdint>

// Problem constants
#define BATCH     2
#define SEQ       2048
#define DMODEL    2048
#define NHEADS    16
#define DK        128
#define MTOT      (BATCH * SEQ)          // 4096
#define LORA_SCALING 2.0f
#define SM_SCALE  0.08838834764831845f   // 1/sqrt(128)
#define NBH       (BATCH * NHEADS)       // 32

// ---------------------------------------------------------------------------
// Scratch buffers (fp16 hi/lo)
// ---------------------------------------------------------------------------
#define HSZ (BATCH * NHEADS * SEQ * DK)  // 8388608
__device__ float g_t_qkv[MTOT * 24];
__device__ float g_t_o[MTOT * 8];
__device__ __half g_xhi[MTOT * DMODEL];
__device__ __half g_xlo[MTOT * DMODEL];
__device__ __half g_whi[4ull * DMODEL * DMODEL];   // hi only (2-product GEMM)
__device__ __half g_chi[MTOT * DMODEL];
__device__ __half g_clo[MTOT * DMODEL];
__device__ __half g_qhi[HSZ], g_qlo[HSZ];
__device__ __half g_khi[HSZ];                      // K: hi only (QK 2-product)
__device__ __half g_vhi[HSZ], g_vlo[HSZ];
__device__ __half g_vthi[HSZ], g_vtlo[HSZ];

// ---------------------------------------------------------------------------
// PTX helpers
// ---------------------------------------------------------------------------
__device__ __forceinline__ void cp16(uint32_t sm_dst, const void* g_src) {
    asm volatile("cp.async.cg.shared.global [%0], [%1], 16;" :: "r"(sm_dst), "l"(g_src) : "memory");
}
#define CP_COMMIT() asm volatile("cp.async.commit_group;" ::: "memory")
#define CP_WAIT(n)  asm volatile("cp.async.wait_group %0;" :: "n"(n) : "memory")

__device__ __forceinline__ uint32_t smem_u32(const void* p) {
    uint32_t a;
    asm("{ .reg .u64 t; cvta.to.shared.u64 t, %1; cvt.u32.u64 %0, t; }" : "=r"(a) : "l"(p));
    return a;
}
#define LDSM_X4(r0, r1, r2, r3, addr) \
    asm volatile("ldmatrix.sync.aligned.m8n8.x4.shared.b16 {%0,%1,%2,%3}, [%4];" \
        : "=r"(r0), "=r"(r1), "=r"(r2), "=r"(r3) : "r"(addr))

#define MMA16816(d, a, b) \
    asm volatile("mma.sync.aligned.m16n8k16.row.col.f32.f16.f16.f32 " \
        "{%0,%1,%2,%3}, {%4,%5,%6,%7}, {%8,%9}, {%0,%1,%2,%3};" \
        : "+f"((d)[0]), "+f"((d)[1]), "+f"((d)[2]), "+f"((d)[3]) \
        : "r"((a)[0]), "r"((a)[1]), "r"((a)[2]), "r"((a)[3]), \
          "r"((b)[0]), "r"((b)[1]))

__device__ __forceinline__ void split2(float a, float b, uint32_t& hi, uint32_t& lo) {
    __half ha = __float2half_rn(a), hb = __float2half_rn(b);
    __half la = __float2half_rn(a - __half2float(ha));
    __half lb = __float2half_rn(b - __half2float(hb));
    __half2 H = __halves2half2(ha, hb), L = __halves2half2(la, lb);
    hi = *(uint32_t*)&H;
    lo = *(uint32_t*)&L;
}

// ---------------------------------------------------------------------------
// fp32 -> fp16 hi/lo split
// ---------------------------------------------------------------------------
__global__ void __launch_bounds__(256)
split_kernel(const float* __restrict__ src, __half* __restrict__ hi,
             __half* __restrict__ lo, int n4)
{
    int i = blockIdx.x * 256 + threadIdx.x;
    if (i >= n4) return;
    float4 v = ((const float4*)src)[i];
    uint32_t h0, l0, h1, l1;
    split2(v.x, v.y, h0, l0);
    split2(v.z, v.w, h1, l1);
    uint32_t* hp = (uint32_t*)(hi + (size_t)i * 4);
    uint32_t* lp = (uint32_t*)(lo + (size_t)i * 4);
    hp[0] = h0; hp[1] = h1;
    lp[0] = l0; lp[1] = l1;
}

// fp32 -> fp16 (hi only, for weights)
__global__ void __launch_bounds__(256)
split_hi_kernel(const float* __restrict__ src, __half* __restrict__ hi, int n4)
{
    int i = blockIdx.x * 256 + threadIdx.x;
    if (i >= n4) return;
    float4 v = ((const float4*)src)[i];
    __half2 a = __halves2half2(__float2half_rn(v.x), __float2half_rn(v.y));
    __half2 b = __halves2half2(__float2half_rn(v.z), __float2half_rn(v.w));
    uint32_t* hp = (uint32_t*)(hi + (size_t)i * 4);
    hp[0] = *(uint32_t*)&a;
    hp[1] = *(uint32_t*)&b;
}

// ---------------------------------------------------------------------------
// LoRA intermediate T[m][o] = sum_k X[m][k] * A_(o/8)[o%8][k]  (fp32 X)
// ---------------------------------------------------------------------------
template <int NOUT>
__global__ void __launch_bounds__(256)
lora_kernel(const float* __restrict__ X,
            const float* __restrict__ A0, const float* __restrict__ A1,
            const float* __restrict__ A2, float* __restrict__ T)
{
    __shared__ float sA[NOUT * 512];
    const int tid   = threadIdx.x;
    const int row   = tid >> 4;
    const int slice = tid & 15;
    const int m     = blockIdx.x * 16 + row;
    const float* Aps[3] = {A0, A1, A2};

    float acc[NOUT];
#pragma unroll
    for (int o = 0; o < NOUT; o++) acc[o] = 0.0f;

    for (int c = 0; c < 4; c++) {
        const int k0 = c * 512;
        for (int i = tid; i < NOUT * 512; i += 256) {
            int o = i >> 9, kk = i & 511;
            const float* Ap = Aps[o >> 3];
            sA[i] = Ap[(o & 7) * DMODEL + k0 + kk];
        }
        __syncthreads();
        const float* xr = X + (size_t)m * DMODEL + k0;
#pragma unroll 4
        for (int j = 0; j < 32; j++) {
            int kk = slice + j * 16;
            float xv = xr[kk];
#pragma unroll
            for (int o = 0; o < NOUT; o++) acc[o] += xv * sA[o * 512 + kk];
        }
        __syncthreads();
    }
#pragma unroll
    for (int o = 0; o < NOUT; o++) {
        float v = acc[o];
        v += __shfl_xor_sync(0xffffffffu, v, 1);
        v += __shfl_xor_sync(0xffffffffu, v, 2);
        v += __shfl_xor_sync(0xffffffffu, v, 4);
        v += __shfl_xor_sync(0xffffffffu, v, 8);
        if (slice == 0) T[(size_t)m * NOUT + o] = v;
    }
}

// fp16 hi/lo input variant (for ctx)
template <int NOUT>
__global__ void __launch_bounds__(256)
lora_h_kernel(const __half* __restrict__ XH, const __half* __restrict__ XL,
              const float* __restrict__ A0, float* __restrict__ T)
{
    __shared__ float sA[NOUT * 512];
    const int tid   = threadIdx.x;
    const int row   = tid >> 4;
    const int slice = tid & 15;
    const int m     = blockIdx.x * 16 + row;

    float acc[NOUT];
#pragma unroll
    for (int o = 0; o < NOUT; o++) acc[o] = 0.0f;

    for (int c = 0; c < 4; c++) {
        const int k0 = c * 512;
        for (int i = tid; i < NOUT * 512; i += 256) {
            int o = i >> 9, kk = i & 511;
            sA[i] = A0[o * DMODEL + k0 + kk];
        }
        __syncthreads();
        const __half* xh = XH + (size_t)m * DMODEL + k0;
        const __half* xl = XL + (size_t)m * DMODEL + k0;
#pragma unroll 4
        for (int j = 0; j < 32; j++) {
            int kk = slice + j * 16;
            float xv = __half2float(xh[kk]) + __half2float(xl[kk]);
#pragma unroll
            for (int o = 0; o < NOUT; o++) acc[o] += xv * sA[o * 512 + kk];
        }
        __syncthreads();
    }
#pragma unroll
    for (int o = 0; o < NOUT; o++) {
        float v = acc[o];
        v += __shfl_xor_sync(0xffffffffu, v, 1);
        v += __shfl_xor_sync(0xffffffffu, v, 2);
        v += __shfl_xor_sync(0xffffffffu, v, 4);
        v += __shfl_xor_sync(0xffffffffu, v, 8);
        if (slice == 0) T[(size_t)m * NOUT + o] = v;
    }
}

// ---------------------------------------------------------------------------
// mma.sync GEMM (fp16 two-product). 128x128 tile, 8 warps, K-block 64,
// two-stage cp.async, ldmatrix loads.
// MODE 0: single matrix, fp32 out. MODE 1: FUSED QKV (N=6144; K writes hi only).
// ---------------------------------------------------------------------------
#define GKB        64
#define ROWB       144
#define MAT_BYTES  (128 * ROWB)          // 18432
#define STAGE_B    (3 * MAT_BYTES)       // 55296 (Ahi|Alo|Whi)
#define GEMM_SMEM  (2 * STAGE_B)         // 110592
#define NKITER     (DMODEL / GKB)        // 32

__device__ __forceinline__ void gemm_load_stage(
    uint32_t sbase, int tid, int s,
    const __half* gAh, const __half* gAl, const __half* gBh)
{
    const uint32_t base = sbase + (s & 1) * STAGE_B;
    const int kt = s * GKB;
    const __half* srcs[3] = {gAh, gAl, gBh};
#pragma unroll
    for (int mat = 0; mat < 3; mat++) {
        const __half* g = srcs[mat];
        uint32_t mbase = base + mat * MAT_BYTES;
#pragma unroll
        for (int t = 0; t < 4; t++) {
            int chunk = tid + t * 256;
            int row = chunk >> 3;
            int cc  = chunk & 7;
            cp16(mbase + row * ROWB + cc * 16,
                 g + (size_t)row * DMODEL + kt + cc * 8);
        }
    }
    CP_COMMIT();
}

template <int MODE>
__global__ void __launch_bounds__(256)
gemm_mma_kernel(const __half* __restrict__ Ahi, const __half* __restrict__ Alo,
                const __half* __restrict__ Bhi,
                const float* __restrict__ bias0, const float* __restrict__ bias1,
                const float* __restrict__ bias2,
                const float* __restrict__ T,
                const float* __restrict__ Bm0, const float* __restrict__ Bm1,
                const float* __restrict__ Bm2,
                float* __restrict__ YoutF,
                __half* __restrict__ YH0, __half* __restrict__ YL0,
                __half* __restrict__ YH1, __half* __restrict__ YL1,
                __half* __restrict__ YH2, __half* __restrict__ YL2,
                int tstride)
{
    extern __shared__ __align__(16) char smem[];
    uint32_t sbase = smem_u32(smem);
    const int tid  = threadIdx.x;
    const int wid  = tid >> 5;
    const int lane = tid & 31;
    const int g    = lane >> 2;
    const int t4   = lane & 3;
    const int wm   = (wid & 1) * 64;
    const int wn   = (wid >> 1) * 32;
    const int m0  = blockIdx.y * 128;
    const int n0g = blockIdx.x * 128;
    const int mat = (MODE == 1) ? (n0g >> 11) : 0;
    const int n0  = n0g & 2047;
    const int toff = (MODE == 1) ? mat * 8 : 0;

    const float* biasP = (mat == 0) ? bias0 : (mat == 1) ? bias1 : bias2;
    const float* BmP   = (mat == 0) ? Bm0   : (mat == 1) ? Bm1   : Bm2;
    __half* YH = (mat == 0) ? YH0 : (mat == 1) ? YH1 : YH2;
    __half* YL = (mat == 0) ? YL0 : (mat == 1) ? YL1 : YL2;

    const int lrow = lane & 7;
    const uint32_t aLane = (uint32_t)((wm + ((lane >> 3) & 1) * 8 + lrow) * ROWB + (lane >> 4) * 16);
    const uint32_t bLane = (uint32_t)((wn + ((lane >> 4) & 1) * 8 + lrow) * ROWB + ((lane >> 3) & 1) * 16);

    const __half* gAh = Ahi + (size_t)m0 * DMODEL;
    const __half* gAl = Alo + (size_t)m0 * DMODEL;
    const __half* gBh = Bhi + (size_t)n0g * DMODEL;

    float acc[4][4][4];
#pragma unroll
    for (int i = 0; i < 4; i++)
#pragma unroll
        for (int j = 0; j < 4; j++)
#pragma unroll
            for (int r = 0; r < 4; r++) acc[i][j][r] = 0.0f;

    gemm_load_stage(sbase, tid, 0, gAh, gAl, gBh);
    gemm_load_stage(sbase, tid, 1, gAh, gAl, gBh);

    for (int s = 0; s < NKITER; s++) {
        if (s == NKITER - 1) { CP_WAIT(0); } else { CP_WAIT(1); }
        __syncthreads();

        const uint32_t st = sbase + (s & 1) * STAGE_B;
        const uint32_t aHiA = st + aLane;
        const uint32_t aLoA = aHiA + MAT_BYTES;
        const uint32_t bHiA = st + 2 * MAT_BYTES + bLane;

#pragma unroll
        for (int kh = 0; kh < 4; kh++) {
            const uint32_t ko = kh * 32;
            uint32_t ah[4][4], al[4][4], bh[4][2];
#pragma unroll
            for (int mi = 0; mi < 4; mi++)
                LDSM_X4(ah[mi][0], ah[mi][1], ah[mi][2], ah[mi][3],
                        aHiA + mi * (16 * ROWB) + ko);
#pragma unroll
            for (int p = 0; p < 2; p++)
                LDSM_X4(bh[2 * p][0], bh[2 * p][1], bh[2 * p + 1][0], bh[2 * p + 1][1],
                        bHiA + p * (16 * ROWB) + ko);
#pragma unroll
            for (int mi = 0; mi < 4; mi++)
#pragma unroll
                for (int ni = 0; ni < 4; ni++)
                    MMA16816(acc[mi][ni], ah[mi], bh[ni]);

#pragma unroll
            for (int mi = 0; mi < 4; mi++)
                LDSM_X4(al[mi][0], al[mi][1], al[mi][2], al[mi][3],
                        aLoA + mi * (16 * ROWB) + ko);
#pragma unroll
            for (int mi = 0; mi < 4; mi++)
#pragma unroll
                for (int ni = 0; ni < 4; ni++)
                    MMA16816(acc[mi][ni], al[mi], bh[ni]);
        }

        __syncthreads();
        if (s + 2 < NKITER)
            gemm_load_stage(sbase, tid, s + 2, gAh, gAl, gBh);
    }

    // Epilogue
    __syncthreads();
    float* sT = (float*)smem;
    float* sB = (float*)(smem + 4096);
    {
        int row = tid >> 1;
        int half = tid & 1;
        float4 tv = *(const float4*)&T[(size_t)(m0 + row) * tstride + toff + half * 4];
        *(float4*)&sT[row * 8 + half * 4] = tv;
        float4 bv = *(const float4*)&BmP[(size_t)(n0 + row) * 8 + half * 4];
        *(float4*)&sB[row * 8 + half * 4] = bv;
    }
    __syncthreads();

    const bool wantLo = (MODE == 0) || (YL != nullptr);
#pragma unroll
    for (int mi = 0; mi < 4; mi++) {
        int rl0 = wm + mi * 16 + g;
#pragma unroll
        for (int rr = 0; rr < 2; rr++) {
            int rl = rl0 + rr * 8;
            int m = m0 + rl;
            const float* tr = &sT[rl * 8];
#pragma unroll
            for (int ni = 0; ni < 4; ni++) {
                int cl = wn + ni * 8 + t4 * 2;
                int n = n0 + cl;
                float d0 = acc[mi][ni][rr * 2 + 0];
                float d1 = acc[mi][ni][rr * 2 + 1];
                const float* b0 = &sB[cl * 8];
                const float* b1 = &sB[(cl + 1) * 8];
                float dot0 = 0.0f, dot1 = 0.0f;
#pragma unroll
                for (int r = 0; r < 8; r++) { dot0 += tr[r] * b0[r]; dot1 += tr[r] * b1[r]; }
                float yx = d0 + biasP[n]     + LORA_SCALING * dot0;
                float yy = d1 + biasP[n + 1] + LORA_SCALING * dot1;
                if (MODE == 0) {
                    *(float2*)&YoutF[(size_t)m * DMODEL + n] = make_float2(yx, yy);
                } else {
                    int bb = m >> 11, ss = m & 2047;
                    int h = n >> 7, d = n & 127;
                    size_t idx = ((((size_t)bb * NHEADS + h) * SEQ + ss) << 7) + d;
                    uint32_t hv, lv;
                    split2(yx, yy, hv, lv);
                    *(uint32_t*)&YH[idx] = hv;
                    if (wantLo) *(uint32_t*)&YL[idx] = lv;
                }
            }
        }
    }
}

// ---------------------------------------------------------------------------
// V transpose: [bh][s][d] -> [bh][d][s], hi and lo.
// ---------------------------------------------------------------------------
__global__ void __launch_bounds__(256)
vtrans_kernel(const __half* __restrict__ vh, const __half* __restrict__ vl,
              __half* __restrict__ vth, __half* __restrict__ vtl)
{
    __shared__ __half tile[64][65];
    const int tid = threadIdx.x;
    const int bh = blockIdx.z;
    const int s0 = blockIdx.x * 64;
    const int d0 = blockIdx.y * 64;

    const __half* srcs[2] = {vh, vl};
    __half* dsts[2] = {vth, vtl};

#pragma unroll
    for (int pass = 0; pass < 2; pass++) {
        const __half* src = srcs[pass] + ((size_t)bh * SEQ + s0) * DK + d0;
        __half* dst = dsts[pass] + ((size_t)bh * DK + d0) * SEQ + s0;
        {
            int i = tid >> 2;
            int jp = tid & 3;
#pragma unroll
            for (int c = 0; c < 8; c++) {
                int j2 = jp * 8 + c;
                __half2 v = *(const __half2*)(src + (size_t)i * DK + j2 * 2);
                tile[i][j2 * 2] = __low2half(v);
                tile[i][j2 * 2 + 1] = __high2half(v);
            }
        }
        __syncthreads();
        {
            int r = tid >> 5;
            int wp = tid & 31;
#pragma unroll
            for (int p = 0; p < 8; p++) {
                int row = r + p * 8;
                __half2 v = __halves2half2(tile[2 * wp][row], tile[2 * wp + 1][row]);
                *(__half2*)(dst + (size_t)row * SEQ + 2 * wp) = v;
            }
        }
        __syncthreads();
    }
}

// ---------------------------------------------------------------------------
// Flash attention: QK 2-product (K hi only), PV 3-product, ldmatrix loads.
// Writes ctx as fp16 hi/lo directly.
// ---------------------------------------------------------------------------
#define FQROW  272
#define FQSZ   (128 * FQROW)
#define FQSZ2  (2 * FQSZ)
#define FKSZ   (64 * FQROW)              // K hi only
#define FVROW  144
#define FVSZ   (128 * FVROW)
#define FSTAGE (FKSZ + 2 * FVSZ)         // 54272
#define FLASH_SMEM (FQSZ2 + 2 * FSTAGE)  // 178176
#define NKVT   (SEQ / 64)

__device__ __forceinline__ void flash_load_stage(
    uint32_t sbase, int tid, int j,
    const __half* Kh, const __half* VTh, const __half* VTl)
{
    const uint32_t st = sbase + FQSZ2 + (j & 1) * FSTAGE;
    const int kv0 = j * 64;
#pragma unroll
    for (int w = 0; w < 4; w++) {            // K hi: 64 rows x 16 chunks
        int chunk = tid + w * 256;
        int row = chunk >> 4;
        int c   = chunk & 15;
        cp16(st + row * FQROW + c * 16,
             Kh + (size_t)(kv0 + row) * DK + c * 8);
    }
#pragma unroll
    for (int w = 0; w < 4; w++) {            // VT hi+lo: 128 rows x 8 chunks
        int chunk = tid + w * 256;
        int row = chunk >> 3;
        int c   = chunk & 7;
        size_t go = (size_t)row * SEQ + kv0 + c * 8;
        cp16(st + FKSZ + row * FVROW + c * 16, VTh + go);
        cp16(st + FKSZ + FVSZ + row * FVROW + c * 16, VTl + go);
    }
    CP_COMMIT();
}

__global__ void __launch_bounds__(256)
flash_mma_kernel(const __half* __restrict__ Qhi, const __half* __restrict__ Qlo,
                 const __half* __restrict__ Khi,
                 const __half* __restrict__ VThi, const __half* __restrict__ VTlo,
                 __half* __restrict__ CH, __half* __restrict__ CL)
{
    extern __shared__ __align__(16) char smem[];
    uint32_t sbase = smem_u32(smem);
    const int tid  = threadIdx.x;
    const int wid  = tid >> 5;
    const int lane = tid & 31;
    const int g    = lane >> 2;
    const int t4   = lane & 3;
    const int wm   = wid * 16;
    const int bh = blockIdx.y;
    const int q0 = blockIdx.x * 128;

    const int lrow = lane & 7;
    const uint32_t qLane = (uint32_t)((wm + ((lane >> 3) & 1) * 8 + lrow) * FQROW + (lane >> 4) * 16);
    const uint32_t kLane = (uint32_t)((((lane >> 4) & 1) * 8 + lrow) * FQROW + ((lane >> 3) & 1) * 16);
    const uint32_t vLane = (uint32_t)((((lane >> 4) & 1) * 8 + lrow) * FVROW + ((lane >> 3) & 1) * 16);

    const __half* Qh = Qhi + ((size_t)bh * SEQ + q0) * DK;
    const __half* Ql = Qlo + ((size_t)bh * SEQ + q0) * DK;
    const __half* Kh = Khi + (size_t)bh * SEQ * DK;
    const __half* Vh = VThi + (size_t)bh * DK * SEQ;
    const __half* Vl = VTlo + (size_t)bh * DK * SEQ;

#pragma unroll
    for (int w = 0; w < 8; w++) {
        int chunk = tid + w * 256;
        int row = chunk >> 4;
        int c   = chunk & 15;
        size_t go = (size_t)row * DK + c * 8;
        cp16(sbase + row * FQROW + c * 16, Qh + go);
        cp16(sbase + FQSZ + row * FQROW + c * 16, Ql + go);
    }
    flash_load_stage(sbase, tid, 0, Kh, Vh, Vl);
    flash_load_stage(sbase, tid, 1, Kh, Vh, Vl);

    float m0 = -INFINITY, m1 = -INFINITY, l0 = 0.0f, l1 = 0.0f;
    float oacc[16][4];
#pragma unroll
    for (int i = 0; i < 16; i++)
#pragma unroll
        for (int r = 0; r < 4; r++) oacc[i][r] = 0.0f;

    for (int j = 0; j < NKVT; j++) {
        if (j == NKVT - 1) { CP_WAIT(0); } else { CP_WAIT(1); }
        __syncthreads();
        const uint32_t st = sbase + FQSZ2 + (j & 1) * FSTAGE;

        float sacc[8][4];
#pragma unroll
        for (int nb = 0; nb < 8; nb++)
#pragma unroll
            for (int r = 0; r < 4; r++) sacc[nb][r] = 0.0f;

        // ---- QK (2 products: (qh+ql) * fp16(K)) ----
#pragma unroll
        for (int kb = 0; kb < 8; kb++) {
            const uint32_t ko = kb * 32;
            uint32_t qh[4], ql[4];
            LDSM_X4(qh[0], qh[1], qh[2], qh[3], sbase + qLane + ko);
            LDSM_X4(ql[0], ql[1], ql[2], ql[3], sbase + FQSZ + qLane + ko);
#pragma unroll
            for (int p = 0; p < 4; p++) {
                uint32_t bhF[2][2];
                uint32_t ka = st + kLane + p * (16 * FQROW) + ko;
                LDSM_X4(bhF[0][0], bhF[0][1], bhF[1][0], bhF[1][1], ka);
#pragma unroll
                for (int q = 0; q < 2; q++) {
                    int nb = 2 * p + q;
                    MMA16816(sacc[nb], qh, bhF[q]);
                    MMA16816(sacc[nb], ql, bhF[q]);
                }
            }
        }

        float mx0 = -INFINITY, mx1 = -INFINITY;
#pragma unroll
        for (int nb = 0; nb < 8; nb++) {
#pragma unroll
            for (int r = 0; r < 4; r++) sacc[nb][r] *= SM_SCALE;
            mx0 = fmaxf(mx0, fmaxf(sacc[nb][0], sacc[nb][1]));
            mx1 = fmaxf(mx1, fmaxf(sacc[nb][2], sacc[nb][3]));
        }
        mx0 = fmaxf(mx0, __shfl_xor_sync(0xffffffffu, mx0, 1));
        mx0 = fmaxf(mx0, __shfl_xor_sync(0xffffffffu, mx0, 2));
        mx1 = fmaxf(mx1, __shfl_xor_sync(0xffffffffu, mx1, 1));
        mx1 = fmaxf(mx1, __shfl_xor_sync(0xffffffffu, mx1, 2));

        float mn0 = fmaxf(m0, mx0), mn1 = fmaxf(m1, mx1);
        float sc0 = __expf(m0 - mn0), sc1 = __expf(m1 - mn1);
        m0 = mn0; m1 = mn1;

        float rs0 = 0.0f, rs1 = 0.0f;
#pragma unroll
        for (int nb = 0; nb < 8; nb++) {
            float p0 = __expf(sacc[nb][0] - mn0);
            float p1 = __expf(sacc[nb][1] - mn0);
            float p2 = __expf(sacc[nb][2] - mn1);
            float p3 = __expf(sacc[nb][3] - mn1);
            sacc[nb][0] = p0; sacc[nb][1] = p1; sacc[nb][2] = p2; sacc[nb][3] = p3;
            rs0 += p0 + p1; rs1 += p2 + p3;
        }
        rs0 += __shfl_xor_sync(0xffffffffu, rs0, 1);
        rs0 += __shfl_xor_sync(0xffffffffu, rs0, 2);
        rs1 += __shfl_xor_sync(0xffffffffu, rs1, 1);
        rs1 += __shfl_xor_sync(0xffffffffu, rs1, 2);
        l0 = l0 * sc0 + rs0;
        l1 = l1 * sc1 + rs1;

#pragma unroll
        for (int nb = 0; nb < 16; nb++) {
            oacc[nb][0] *= sc0; oacc[nb][1] *= sc0;
            oacc[nb][2] *= sc1; oacc[nb][3] *= sc1;
        }

        uint32_t ph[4][4], pl[4][4];
#pragma unroll
        for (int kb = 0; kb < 4; kb++) {
            split2(sacc[2 * kb][0],     sacc[2 * kb][1],     ph[kb][0], pl[kb][0]);
            split2(sacc[2 * kb][2],     sacc[2 * kb][3],     ph[kb][1], pl[kb][1]);
            split2(sacc[2 * kb + 1][0], sacc[2 * kb + 1][1], ph[kb][2], pl[kb][2]);
            split2(sacc[2 * kb + 1][2], sacc[2 * kb + 1][3], ph[kb][3], pl[kb][3]);
        }

        // ---- PV (3 products) ----
        const uint32_t vb = st + FKSZ;
#pragma unroll
        for (int kb = 0; kb < 4; kb++) {
            const uint32_t ko = kb * 32;
#pragma unroll
            for (int p = 0; p < 8; p++) {
                uint32_t bhF[2][2], blF[2][2];
                uint32_t va = vb + vLane + p * (16 * FVROW) + ko;
                LDSM_X4(bhF[0][0], bhF[0][1], bhF[1][0], bhF[1][1], va);
                LDSM_X4(blF[0][0], blF[0][1], blF[1][0], blF[1][1], va + FVSZ);
#pragma unroll
                for (int q = 0; q < 2; q++) {
                    int nb = 2 * p + q;
                    MMA16816(oacc[nb], ph[kb], bhF[q]);
                    MMA16816(oacc[nb], ph[kb], blF[q]);
                    MMA16816(oacc[nb], pl[kb], bhF[q]);
                }
            }
        }

        __syncthreads();
        if (j + 2 < NKVT)
            flash_load_stage(sbase, tid, j + 2, Kh, Vh, Vl);
    }

    // write ctx fp16 hi/lo token-major: [b*S+s][h*128+d]
    const int b = bh >> 4;
    const int h = bh & 15;
    const float inv0 = 1.0f / l0;
    const float inv1 = 1.0f / l1;
    const int s0r = q0 + wm + g;
    size_t idx0 = ((size_t)(b * SEQ + s0r)) * DMODEL + h * DK;
    size_t idx1 = ((size_t)(b * SEQ + s0r + 8)) * DMODEL + h * DK;
#pragma unroll
    for (int nb = 0; nb < 16; nb++) {
        int d = nb * 8 + t4 * 2;
        uint32_t hv, lv;
        split2(oacc[nb][0] * inv0, oacc[nb][1] * inv0, hv, lv);
        *(uint32_t*)&CH[idx0 + d] = hv;
        *(uint32_t*)&CL[idx0 + d] = lv;
        split2(oacc[nb][2] * inv1, oacc[nb][3] * inv1, hv, lv);
        *(uint32_t*)&CH[idx1 + d] = hv;
        *(uint32_t*)&CL[idx1 + d] = lv;
    }
}

// ---------------------------------------------------------------------------
// Launch
// ---------------------------------------------------------------------------
extern "C" void kernel_launch(void* const* d_in, const int* in_sizes, int n_in,
                              void* d_out, int out_size)
{
    const float* x  = (const float*)d_in[0];
    const float* Wq = (const float*)d_in[1];
    const float* bq = (const float*)d_in[2];
    const float* Aq = (const float*)d_in[3];
    const float* Bq = (const float*)d_in[4];
    const float* Wk = (const float*)d_in[5];
    const float* bk = (const float*)d_in[6];
    const float* Ak = (const float*)d_in[7];
    const float* Bk = (const float*)d_in[8];
    const float* Wv = (const float*)d_in[9];
    const float* bv = (const float*)d_in[10];
    const float* Av = (const float*)d_in[11];
    const float* Bv = (const float*)d_in[12];
    const float* Wo = (const float*)d_in[13];
    const float* bo = (const float*)d_in[14];
    const float* Ao = (const float*)d_in[15];
    const float* Bo = (const float*)d_in[16];
    float* out = (float*)d_out;

    float *pt, *pto;
    __half *pxhi, *pxlo, *pwhi, *pchi, *pclo;
    __half *pqhi, *pqlo, *pkhi, *pvhi, *pvlo, *pvthi, *pvtlo;
    cudaGetSymbolAddress((void**)&pt,   g_t_qkv);
    cudaGetSymbolAddress((void**)&pto,  g_t_o);
    cudaGetSymbolAddress((void**)&pxhi, g_xhi);
    cudaGetSymbolAddress((void**)&pxlo, g_xlo);
    cudaGetSymbolAddress((void**)&pwhi, g_whi);
    cudaGetSymbolAddress((void**)&pchi, g_chi);
    cudaGetSymbolAddress((void**)&pclo, g_clo);
    cudaGetSymbolAddress((void**)&pqhi, g_qhi);
    cudaGetSymbolAddress((void**)&pqlo, g_qlo);
    cudaGetSymbolAddress((void**)&pkhi, g_khi);
    cudaGetSymbolAddress((void**)&pvhi, g_vhi);
    cudaGetSymbolAddress((void**)&pvlo, g_vlo);
    cudaGetSymbolAddress((void**)&pvthi, g_vthi);
    cudaGetSymbolAddress((void**)&pvtlo, g_vtlo);

    cudaFuncSetAttribute(gemm_mma_kernel<0>,
                         cudaFuncAttributeMaxDynamicSharedMemorySize, GEMM_SMEM);
    cudaFuncSetAttribute(gemm_mma_kernel<1>,
                         cudaFuncAttributeMaxDynamicSharedMemorySize, GEMM_SMEM);
    cudaFuncSetAttribute(flash_mma_kernel,
                         cudaFuncAttributeMaxDynamicSharedMemorySize, FLASH_SMEM);

    const size_t WSZ = (size_t)DMODEL * DMODEL;
    const int nX4 = MTOT * DMODEL / 4;
    const int nW4 = (int)(WSZ / 4);
    const int sg  = 256;

    // 1) Splits (x hi/lo; weights hi only)
    split_kernel<<<(nX4 + sg - 1) / sg, sg>>>(x, pxhi, pxlo, nX4);
    split_hi_kernel<<<(nW4 + sg - 1) / sg, sg>>>(Wq, pwhi + 0 * WSZ, nW4);
    split_hi_kernel<<<(nW4 + sg - 1) / sg, sg>>>(Wk, pwhi + 1 * WSZ, nW4);
    split_hi_kernel<<<(nW4 + sg - 1) / sg, sg>>>(Wv, pwhi + 2 * WSZ, nW4);
    split_hi_kernel<<<(nW4 + sg - 1) / sg, sg>>>(Wo, pwhi + 3 * WSZ, nW4);

    // 2) LoRA intermediates (q|k|v)
    lora_kernel<24><<<MTOT / 16, 256>>>(x, Aq, Ak, Av, pt);

    // 3) FUSED QKV projection (K writes hi only)
    dim3 gQKV(3 * DMODEL / 128, MTOT / 128);   // (48, 32)
    gemm_mma_kernel<1><<<gQKV, 256, GEMM_SMEM>>>(
        pxhi, pxlo, pwhi,
        bq, bk, bv, pt, Bq, Bk, Bv,
        nullptr,
        pqhi, pqlo, pkhi, nullptr, pvhi, pvlo, 24);

    // 4) V transpose
    dim3 tgrid(SEQ / 64, DK / 64, NBH);
    vtrans_kernel<<<tgrid, 256>>>(pvhi, pvlo, pvthi, pvtlo);

    // 5) Flash attention -> ctx fp16 hi/lo
    dim3 fgrid(SEQ / 128, NBH);
    flash_mma_kernel<<<fgrid, 256, FLASH_SMEM>>>(pqhi, pqlo, pkhi, pvthi, pvtlo,
                                                 pchi, pclo);

    // 6) Output projection (ctx consumed directly as fp16 hi/lo)
    lora_h_kernel<8><<<MTOT / 16, 256>>>(pchi, pclo, Ao, pto);
    dim3 gO(DMODEL / 128, MTOT / 128);         // (16, 32)
    gemm_mma_kernel<0><<<gO, 256, GEMM_SMEM>>>(
        pchi, pclo, pwhi + 3 * WSZ,
        bo, bo, bo, pto, Bo, Bo, Bo,
        out,
        nullptr, nullptr, nullptr, nullptr, nullptr, nullptr, 8);
}

// round 17
// speedup vs baseline: 1.3401x; 1.0646x over previous
#include <cuda_runtime.h>
#include <cuda_fp16.h>
#include <math.h>
#include <cstdint>

// Problem constants
#define BATCH     2
#define SEQ       2048
#define DMODEL    2048
#define NHEADS    16
#define DK        128
#define MTOT      (BATCH * SEQ)          // 4096
#define LORA_SCALING 2.0f
#define SM_SCALE  0.08838834764831845f   // 1/sqrt(128)
#define NBH       (BATCH * NHEADS)       // 32

// ---------------------------------------------------------------------------
// Scratch buffers (fp16 hi/lo)
// ---------------------------------------------------------------------------
#define HSZ (BATCH * NHEADS * SEQ * DK)  // 8388608
__device__ float g_t_qkv[MTOT * 24];
__device__ float g_t_o[MTOT * 8];
__device__ __half g_xhi[MTOT * DMODEL];
__device__ __half g_xlo[MTOT * DMODEL];
__device__ __half g_whi[4ull * DMODEL * DMODEL];   // hi only
__device__ __half g_chi[MTOT * DMODEL];
__device__ __half g_clo[MTOT * DMODEL];
__device__ __half g_qhi[HSZ], g_qlo[HSZ];
__device__ __half g_khi[HSZ];                      // K: hi only
__device__ __half g_vhi[HSZ];                      // V: hi only
__device__ __half g_vthi[HSZ];                     // V^T: hi only

// ---------------------------------------------------------------------------
// PTX helpers
// ---------------------------------------------------------------------------
__device__ __forceinline__ void cp16(uint32_t sm_dst, const void* g_src) {
    asm volatile("cp.async.cg.shared.global [%0], [%1], 16;" :: "r"(sm_dst), "l"(g_src) : "memory");
}
#define CP_COMMIT() asm volatile("cp.async.commit_group;" ::: "memory")
#define CP_WAIT(n)  asm volatile("cp.async.wait_group %0;" :: "n"(n) : "memory")

__device__ __forceinline__ uint32_t smem_u32(const void* p) {
    uint32_t a;
    asm("{ .reg .u64 t; cvta.to.shared.u64 t, %1; cvt.u32.u64 %0, t; }" : "=r"(a) : "l"(p));
    return a;
}
#define LDSM_X4(r0, r1, r2, r3, addr) \
    asm volatile("ldmatrix.sync.aligned.m8n8.x4.shared.b16 {%0,%1,%2,%3}, [%4];" \
        : "=r"(r0), "=r"(r1), "=r"(r2), "=r"(r3) : "r"(addr))

#define MMA16816(d, a, b) \
    asm volatile("mma.sync.aligned.m16n8k16.row.col.f32.f16.f16.f32 " \
        "{%0,%1,%2,%3}, {%4,%5,%6,%7}, {%8,%9}, {%0,%1,%2,%3};" \
        : "+f"((d)[0]), "+f"((d)[1]), "+f"((d)[2]), "+f"((d)[3]) \
        : "r"((a)[0]), "r"((a)[1]), "r"((a)[2]), "r"((a)[3]), \
          "r"((b)[0]), "r"((b)[1]))

__device__ __forceinline__ void split2(float a, float b, uint32_t& hi, uint32_t& lo) {
    __half ha = __float2half_rn(a), hb = __float2half_rn(b);
    __half la = __float2half_rn(a - __half2float(ha));
    __half lb = __float2half_rn(b - __half2float(hb));
    __half2 H = __halves2half2(ha, hb), L = __halves2half2(la, lb);
    hi = *(uint32_t*)&H;
    lo = *(uint32_t*)&L;
}

// ---------------------------------------------------------------------------
// fp32 -> fp16 hi/lo split
// ---------------------------------------------------------------------------
__global__ void __launch_bounds__(256)
split_kernel(const float* __restrict__ src, __half* __restrict__ hi,
             __half* __restrict__ lo, int n4)
{
    int i = blockIdx.x * 256 + threadIdx.x;
    if (i >= n4) return;
    float4 v = ((const float4*)src)[i];
    uint32_t h0, l0, h1, l1;
    split2(v.x, v.y, h0, l0);
    split2(v.z, v.w, h1, l1);
    uint32_t* hp = (uint32_t*)(hi + (size_t)i * 4);
    uint32_t* lp = (uint32_t*)(lo + (size_t)i * 4);
    hp[0] = h0; hp[1] = h1;
    lp[0] = l0; lp[1] = l1;
}

// fp32 -> fp16 (hi only, for weights)
__global__ void __launch_bounds__(256)
split_hi_kernel(const float* __restrict__ src, __half* __restrict__ hi, int n4)
{
    int i = blockIdx.x * 256 + threadIdx.x;
    if (i >= n4) return;
    float4 v = ((const float4*)src)[i];
    __half2 a = __halves2half2(__float2half_rn(v.x), __float2half_rn(v.y));
    __half2 b = __halves2half2(__float2half_rn(v.z), __float2half_rn(v.w));
    uint32_t* hp = (uint32_t*)(hi + (size_t)i * 4);
    hp[0] = *(uint32_t*)&a;
    hp[1] = *(uint32_t*)&b;
}

// ---------------------------------------------------------------------------
// LoRA intermediate T[m][o] = sum_k X[m][k] * A_(o/8)[o%8][k]  (fp32 X)
// ---------------------------------------------------------------------------
template <int NOUT>
__global__ void __launch_bounds__(256)
lora_kernel(const float* __restrict__ X,
            const float* __restrict__ A0, const float* __restrict__ A1,
            const float* __restrict__ A2, float* __restrict__ T)
{
    __shared__ float sA[NOUT * 512];
    const int tid   = threadIdx.x;
    const int row   = tid >> 4;
    const int slice = tid & 15;
    const int m     = blockIdx.x * 16 + row;
    const float* Aps[3] = {A0, A1, A2};

    float acc[NOUT];
#pragma unroll
    for (int o = 0; o < NOUT; o++) acc[o] = 0.0f;

    for (int c = 0; c < 4; c++) {
        const int k0 = c * 512;
        for (int i = tid; i < NOUT * 512; i += 256) {
            int o = i >> 9, kk = i & 511;
            const float* Ap = Aps[o >> 3];
            sA[i] = Ap[(o & 7) * DMODEL + k0 + kk];
        }
        __syncthreads();
        const float* xr = X + (size_t)m * DMODEL + k0;
#pragma unroll 4
        for (int j = 0; j < 32; j++) {
            int kk = slice + j * 16;
            float xv = xr[kk];
#pragma unroll
            for (int o = 0; o < NOUT; o++) acc[o] += xv * sA[o * 512 + kk];
        }
        __syncthreads();
    }
#pragma unroll
    for (int o = 0; o < NOUT; o++) {
        float v = acc[o];
        v += __shfl_xor_sync(0xffffffffu, v, 1);
        v += __shfl_xor_sync(0xffffffffu, v, 2);
        v += __shfl_xor_sync(0xffffffffu, v, 4);
        v += __shfl_xor_sync(0xffffffffu, v, 8);
        if (slice == 0) T[(size_t)m * NOUT + o] = v;
    }
}

// fp16 hi/lo input variant (for ctx)
template <int NOUT>
__global__ void __launch_bounds__(256)
lora_h_kernel(const __half* __restrict__ XH, const __half* __restrict__ XL,
              const float* __restrict__ A0, float* __restrict__ T)
{
    __shared__ float sA[NOUT * 512];
    const int tid   = threadIdx.x;
    const int row   = tid >> 4;
    const int slice = tid & 15;
    const int m     = blockIdx.x * 16 + row;

    float acc[NOUT];
#pragma unroll
    for (int o = 0; o < NOUT; o++) acc[o] = 0.0f;

    for (int c = 0; c < 4; c++) {
        const int k0 = c * 512;
        for (int i = tid; i < NOUT * 512; i += 256) {
            int o = i >> 9, kk = i & 511;
            sA[i] = A0[o * DMODEL + k0 + kk];
        }
        __syncthreads();
        const __half* xh = XH + (size_t)m * DMODEL + k0;
        const __half* xl = XL + (size_t)m * DMODEL + k0;
#pragma unroll 4
        for (int j = 0; j < 32; j++) {
            int kk = slice + j * 16;
            float xv = __half2float(xh[kk]) + __half2float(xl[kk]);
#pragma unroll
            for (int o = 0; o < NOUT; o++) acc[o] += xv * sA[o * 512 + kk];
        }
        __syncthreads();
    }
#pragma unroll
    for (int o = 0; o < NOUT; o++) {
        float v = acc[o];
        v += __shfl_xor_sync(0xffffffffu, v, 1);
        v += __shfl_xor_sync(0xffffffffu, v, 2);
        v += __shfl_xor_sync(0xffffffffu, v, 4);
        v += __shfl_xor_sync(0xffffffffu, v, 8);
        if (slice == 0) T[(size_t)m * NOUT + o] = v;
    }
}

// ---------------------------------------------------------------------------
// mma.sync GEMM (fp16 two-product). 128x128 tile, 8 warps, K-block 64,
// two-stage cp.async, ldmatrix loads.
// MODE 0: single matrix, fp32 out. MODE 1: FUSED QKV (K, V write hi only).
// ---------------------------------------------------------------------------
#define GKB        64
#define ROWB       144
#define MAT_BYTES  (128 * ROWB)          // 18432
#define STAGE_B    (3 * MAT_BYTES)       // 55296 (Ahi|Alo|Whi)
#define GEMM_SMEM  (2 * STAGE_B)         // 110592
#define NKITER     (DMODEL / GKB)        // 32

__device__ __forceinline__ void gemm_load_stage(
    uint32_t sbase, int tid, int s,
    const __half* gAh, const __half* gAl, const __half* gBh)
{
    const uint32_t base = sbase + (s & 1) * STAGE_B;
    const int kt = s * GKB;
    const __half* srcs[3] = {gAh, gAl, gBh};
#pragma unroll
    for (int mat = 0; mat < 3; mat++) {
        const __half* g = srcs[mat];
        uint32_t mbase = base + mat * MAT_BYTES;
#pragma unroll
        for (int t = 0; t < 4; t++) {
            int chunk = tid + t * 256;
            int row = chunk >> 3;
            int cc  = chunk & 7;
            cp16(mbase + row * ROWB + cc * 16,
                 g + (size_t)row * DMODEL + kt + cc * 8);
        }
    }
    CP_COMMIT();
}

template <int MODE>
__global__ void __launch_bounds__(256)
gemm_mma_kernel(const __half* __restrict__ Ahi, const __half* __restrict__ Alo,
                const __half* __restrict__ Bhi,
                const float* __restrict__ bias0, const float* __restrict__ bias1,
                const float* __restrict__ bias2,
                const float* __restrict__ T,
                const float* __restrict__ Bm0, const float* __restrict__ Bm1,
                const float* __restrict__ Bm2,
                float* __restrict__ YoutF,
                __half* __restrict__ YH0, __half* __restrict__ YL0,
                __half* __restrict__ YH1, __half* __restrict__ YL1,
                __half* __restrict__ YH2, __half* __restrict__ YL2,
                int tstride)
{
    extern __shared__ __align__(16) char smem[];
    uint32_t sbase = smem_u32(smem);
    const int tid  = threadIdx.x;
    const int wid  = tid >> 5;
    const int lane = tid & 31;
    const int g    = lane >> 2;
    const int t4   = lane & 3;
    const int wm   = (wid & 1) * 64;
    const int wn   = (wid >> 1) * 32;
    const int m0  = blockIdx.y * 128;
    const int n0g = blockIdx.x * 128;
    const int mat = (MODE == 1) ? (n0g >> 11) : 0;
    const int n0  = n0g & 2047;
    const int toff = (MODE == 1) ? mat * 8 : 0;

    const float* biasP = (mat == 0) ? bias0 : (mat == 1) ? bias1 : bias2;
    const float* BmP   = (mat == 0) ? Bm0   : (mat == 1) ? Bm1   : Bm2;
    __half* YH = (mat == 0) ? YH0 : (mat == 1) ? YH1 : YH2;
    __half* YL = (mat == 0) ? YL0 : (mat == 1) ? YL1 : YL2;

    const int lrow = lane & 7;
    const uint32_t aLane = (uint32_t)((wm + ((lane >> 3) & 1) * 8 + lrow) * ROWB + (lane >> 4) * 16);
    const uint32_t bLane = (uint32_t)((wn + ((lane >> 4) & 1) * 8 + lrow) * ROWB + ((lane >> 3) & 1) * 16);

    const __half* gAh = Ahi + (size_t)m0 * DMODEL;
    const __half* gAl = Alo + (size_t)m0 * DMODEL;
    const __half* gBh = Bhi + (size_t)n0g * DMODEL;

    float acc[4][4][4];
#pragma unroll
    for (int i = 0; i < 4; i++)
#pragma unroll
        for (int j = 0; j < 4; j++)
#pragma unroll
            for (int r = 0; r < 4; r++) acc[i][j][r] = 0.0f;

    gemm_load_stage(sbase, tid, 0, gAh, gAl, gBh);
    gemm_load_stage(sbase, tid, 1, gAh, gAl, gBh);

    for (int s = 0; s < NKITER; s++) {
        if (s == NKITER - 1) { CP_WAIT(0); } else { CP_WAIT(1); }
        __syncthreads();

        const uint32_t st = sbase + (s & 1) * STAGE_B;
        const uint32_t aHiA = st + aLane;
        const uint32_t aLoA = aHiA + MAT_BYTES;
        const uint32_t bHiA = st + 2 * MAT_BYTES + bLane;

#pragma unroll
        for (int kh = 0; kh < 4; kh++) {
            const uint32_t ko = kh * 32;
            uint32_t ah[4][4], al[4][4], bh[4][2];
#pragma unroll
            for (int mi = 0; mi < 4; mi++)
                LDSM_X4(ah[mi][0], ah[mi][1], ah[mi][2], ah[mi][3],
                        aHiA + mi * (16 * ROWB) + ko);
#pragma unroll
            for (int p = 0; p < 2; p++)
                LDSM_X4(bh[2 * p][0], bh[2 * p][1], bh[2 * p + 1][0], bh[2 * p + 1][1],
                        bHiA + p * (16 * ROWB) + ko);
#pragma unroll
            for (int mi = 0; mi < 4; mi++)
#pragma unroll
                for (int ni = 0; ni < 4; ni++)
                    MMA16816(acc[mi][ni], ah[mi], bh[ni]);

#pragma unroll
            for (int mi = 0; mi < 4; mi++)
                LDSM_X4(al[mi][0], al[mi][1], al[mi][2], al[mi][3],
                        aLoA + mi * (16 * ROWB) + ko);
#pragma unroll
            for (int mi = 0; mi < 4; mi++)
#pragma unroll
                for (int ni = 0; ni < 4; ni++)
                    MMA16816(acc[mi][ni], al[mi], bh[ni]);
        }

        __syncthreads();
        if (s + 2 < NKITER)
            gemm_load_stage(sbase, tid, s + 2, gAh, gAl, gBh);
    }

    // Epilogue
    __syncthreads();
    float* sT = (float*)smem;
    float* sB = (float*)(smem + 4096);
    {
        int row = tid >> 1;
        int half = tid & 1;
        float4 tv = *(const float4*)&T[(size_t)(m0 + row) * tstride + toff + half * 4];
        *(float4*)&sT[row * 8 + half * 4] = tv;
        float4 bv = *(const float4*)&BmP[(size_t)(n0 + row) * 8 + half * 4];
        *(float4*)&sB[row * 8 + half * 4] = bv;
    }
    __syncthreads();

    const bool wantLo = (MODE == 1) && (YL != nullptr);
#pragma unroll
    for (int mi = 0; mi < 4; mi++) {
        int rl0 = wm + mi * 16 + g;
#pragma unroll
        for (int rr = 0; rr < 2; rr++) {
            int rl = rl0 + rr * 8;
            int m = m0 + rl;
            const float* tr = &sT[rl * 8];
#pragma unroll
            for (int ni = 0; ni < 4; ni++) {
                int cl = wn + ni * 8 + t4 * 2;
                int n = n0 + cl;
                float d0 = acc[mi][ni][rr * 2 + 0];
                float d1 = acc[mi][ni][rr * 2 + 1];
                const float* b0 = &sB[cl * 8];
                const float* b1 = &sB[(cl + 1) * 8];
                float dot0 = 0.0f, dot1 = 0.0f;
#pragma unroll
                for (int r = 0; r < 8; r++) { dot0 += tr[r] * b0[r]; dot1 += tr[r] * b1[r]; }
                float yx = d0 + biasP[n]     + LORA_SCALING * dot0;
                float yy = d1 + biasP[n + 1] + LORA_SCALING * dot1;
                if (MODE == 0) {
                    *(float2*)&YoutF[(size_t)m * DMODEL + n] = make_float2(yx, yy);
                } else {
                    int bb = m >> 11, ss = m & 2047;
                    int h = n >> 7, d = n & 127;
                    size_t idx = ((((size_t)bb * NHEADS + h) * SEQ + ss) << 7) + d;
                    uint32_t hv, lv;
                    split2(yx, yy, hv, lv);
                    *(uint32_t*)&YH[idx] = hv;
                    if (wantLo) *(uint32_t*)&YL[idx] = lv;
                }
            }
        }
    }
}

// ---------------------------------------------------------------------------
// V transpose: [bh][s][d] -> [bh][d][s], hi only.
// ---------------------------------------------------------------------------
__global__ void __launch_bounds__(256)
vtrans_kernel(const __half* __restrict__ vh, __half* __restrict__ vth)
{
    __shared__ __half tile[64][65];
    const int tid = threadIdx.x;
    const int bh = blockIdx.z;
    const int s0 = blockIdx.x * 64;
    const int d0 = blockIdx.y * 64;

    const __half* src = vh + ((size_t)bh * SEQ + s0) * DK + d0;
    __half* dst = vth + ((size_t)bh * DK + d0) * SEQ + s0;
    {
        int i = tid >> 2;
        int jp = tid & 3;
#pragma unroll
        for (int c = 0; c < 8; c++) {
            int j2 = jp * 8 + c;
            __half2 v = *(const __half2*)(src + (size_t)i * DK + j2 * 2);
            tile[i][j2 * 2] = __low2half(v);
            tile[i][j2 * 2 + 1] = __high2half(v);
        }
    }
    __syncthreads();
    {
        int r = tid >> 5;
        int wp = tid & 31;
#pragma unroll
        for (int p = 0; p < 8; p++) {
            int row = r + p * 8;
            __half2 v = __halves2half2(tile[2 * wp][row], tile[2 * wp + 1][row]);
            *(__half2*)(dst + (size_t)row * SEQ + 2 * wp) = v;
        }
    }
}

// ---------------------------------------------------------------------------
// Flash attention: QK 2-product (K hi), PV 2-product (V hi, P split).
// ldmatrix loads. Writes ctx as fp16 hi/lo directly.
// ---------------------------------------------------------------------------
#define FQROW  272
#define FQSZ   (128 * FQROW)
#define FQSZ2  (2 * FQSZ)
#define FKSZ   (64 * FQROW)              // K hi only
#define FVROW  144
#define FVSZ   (128 * FVROW)
#define FSTAGE (FKSZ + FVSZ)             // 35840
#define FLASH_SMEM (FQSZ2 + 2 * FSTAGE)  // 141312
#define NKVT   (SEQ / 64)

__device__ __forceinline__ void flash_load_stage(
    uint32_t sbase, int tid, int j,
    const __half* Kh, const __half* VTh)
{
    const uint32_t st = sbase + FQSZ2 + (j & 1) * FSTAGE;
    const int kv0 = j * 64;
#pragma unroll
    for (int w = 0; w < 4; w++) {            // K hi: 64 rows x 16 chunks
        int chunk = tid + w * 256;
        int row = chunk >> 4;
        int c   = chunk & 15;
        cp16(st + row * FQROW + c * 16,
             Kh + (size_t)(kv0 + row) * DK + c * 8);
    }
#pragma unroll
    for (int w = 0; w < 4; w++) {            // VT hi: 128 rows x 8 chunks
        int chunk = tid + w * 256;
        int row = chunk >> 3;
        int c   = chunk & 7;
        cp16(st + FKSZ + row * FVROW + c * 16,
             VTh + (size_t)row * SEQ + kv0 + c * 8);
    }
    CP_COMMIT();
}

__global__ void __launch_bounds__(256)
flash_mma_kernel(const __half* __restrict__ Qhi, const __half* __restrict__ Qlo,
                 const __half* __restrict__ Khi,
                 const __half* __restrict__ VThi,
                 __half* __restrict__ CH, __half* __restrict__ CL)
{
    extern __shared__ __align__(16) char smem[];
    uint32_t sbase = smem_u32(smem);
    const int tid  = threadIdx.x;
    const int wid  = tid >> 5;
    const int lane = tid & 31;
    const int g    = lane >> 2;
    const int t4   = lane & 3;
    const int wm   = wid * 16;
    const int bh = blockIdx.y;
    const int q0 = blockIdx.x * 128;

    const int lrow = lane & 7;
    const uint32_t qLane = (uint32_t)((wm + ((lane >> 3) & 1) * 8 + lrow) * FQROW + (lane >> 4) * 16);
    const uint32_t kLane = (uint32_t)((((lane >> 4) & 1) * 8 + lrow) * FQROW + ((lane >> 3) & 1) * 16);
    const uint32_t vLane = (uint32_t)((((lane >> 4) & 1) * 8 + lrow) * FVROW + ((lane >> 3) & 1) * 16);

    const __half* Qh = Qhi + ((size_t)bh * SEQ + q0) * DK;
    const __half* Ql = Qlo + ((size_t)bh * SEQ + q0) * DK;
    const __half* Kh = Khi + (size_t)bh * SEQ * DK;
    const __half* Vh = VThi + (size_t)bh * DK * SEQ;

#pragma unroll
    for (int w = 0; w < 8; w++) {
        int chunk = tid + w * 256;
        int row = chunk >> 4;
        int c   = chunk & 15;
        size_t go = (size_t)row * DK + c * 8;
        cp16(sbase + row * FQROW + c * 16, Qh + go);
        cp16(sbase + FQSZ + row * FQROW + c * 16, Ql + go);
    }
    flash_load_stage(sbase, tid, 0, Kh, Vh);
    flash_load_stage(sbase, tid, 1, Kh, Vh);

    float m0 = -INFINITY, m1 = -INFINITY, l0 = 0.0f, l1 = 0.0f;
    float oacc[16][4];
#pragma unroll
    for (int i = 0; i < 16; i++)
#pragma unroll
        for (int r = 0; r < 4; r++) oacc[i][r] = 0.0f;

    for (int j = 0; j < NKVT; j++) {
        if (j == NKVT - 1) { CP_WAIT(0); } else { CP_WAIT(1); }
        __syncthreads();
        const uint32_t st = sbase + FQSZ2 + (j & 1) * FSTAGE;

        float sacc[8][4];
#pragma unroll
        for (int nb = 0; nb < 8; nb++)
#pragma unroll
            for (int r = 0; r < 4; r++) sacc[nb][r] = 0.0f;

        // ---- QK (2 products: (qh+ql) * fp16(K)) ----
#pragma unroll
        for (int kb = 0; kb < 8; kb++) {
            const uint32_t ko = kb * 32;
            uint32_t qh[4], ql[4];
            LDSM_X4(qh[0], qh[1], qh[2], qh[3], sbase + qLane + ko);
            LDSM_X4(ql[0], ql[1], ql[2], ql[3], sbase + FQSZ + qLane + ko);
#pragma unroll
            for (int p = 0; p < 4; p++) {
                uint32_t bhF[2][2];
                uint32_t ka = st + kLane + p * (16 * FQROW) + ko;
                LDSM_X4(bhF[0][0], bhF[0][1], bhF[1][0], bhF[1][1], ka);
#pragma unroll
                for (int q = 0; q < 2; q++) {
                    int nb = 2 * p + q;
                    MMA16816(sacc[nb], qh, bhF[q]);
                    MMA16816(sacc[nb], ql, bhF[q]);
                }
            }
        }

        float mx0 = -INFINITY, mx1 = -INFINITY;
#pragma unroll
        for (int nb = 0; nb < 8; nb++) {
#pragma unroll
            for (int r = 0; r < 4; r++) sacc[nb][r] *= SM_SCALE;
            mx0 = fmaxf(mx0, fmaxf(sacc[nb][0], sacc[nb][1]));
            mx1 = fmaxf(mx1, fmaxf(sacc[nb][2], sacc[nb][3]));
        }
        mx0 = fmaxf(mx0, __shfl_xor_sync(0xffffffffu, mx0, 1));
        mx0 = fmaxf(mx0, __shfl_xor_sync(0xffffffffu, mx0, 2));
        mx1 = fmaxf(mx1, __shfl_xor_sync(0xffffffffu, mx1, 1));
        mx1 = fmaxf(mx1, __shfl_xor_sync(0xffffffffu, mx1, 2));

        float mn0 = fmaxf(m0, mx0), mn1 = fmaxf(m1, mx1);
        float sc0 = __expf(m0 - mn0), sc1 = __expf(m1 - mn1);
        m0 = mn0; m1 = mn1;

        float rs0 = 0.0f, rs1 = 0.0f;
#pragma unroll
        for (int nb = 0; nb < 8; nb++) {
            float p0 = __expf(sacc[nb][0] - mn0);
            float p1 = __expf(sacc[nb][1] - mn0);
            float p2 = __expf(sacc[nb][2] - mn1);
            float p3 = __expf(sacc[nb][3] - mn1);
            sacc[nb][0] = p0; sacc[nb][1] = p1; sacc[nb][2] = p2; sacc[nb][3] = p3;
            rs0 += p0 + p1; rs1 += p2 + p3;
        }
        rs0 += __shfl_xor_sync(0xffffffffu, rs0, 1);
        rs0 += __shfl_xor_sync(0xffffffffu, rs0, 2);
        rs1 += __shfl_xor_sync(0xffffffffu, rs1, 1);
        rs1 += __shfl_xor_sync(0xffffffffu, rs1, 2);
        l0 = l0 * sc0 + rs0;
        l1 = l1 * sc1 + rs1;

#pragma unroll
        for (int nb = 0; nb < 16; nb++) {
            oacc[nb][0] *= sc0; oacc[nb][1] *= sc0;
            oacc[nb][2] *= sc1; oacc[nb][3] *= sc1;
        }

        uint32_t ph[4][4], pl[4][4];
#pragma unroll
        for (int kb = 0; kb < 4; kb++) {
            split2(sacc[2 * kb][0],     sacc[2 * kb][1],     ph[kb][0], pl[kb][0]);
            split2(sacc[2 * kb][2],     sacc[2 * kb][3],     ph[kb][1], pl[kb][1]);
            split2(sacc[2 * kb + 1][0], sacc[2 * kb + 1][1], ph[kb][2], pl[kb][2]);
            split2(sacc[2 * kb + 1][2], sacc[2 * kb + 1][3], ph[kb][3], pl[kb][3]);
        }

        // ---- PV (2 products: (ph+pl) * fp16(V)) ----
        const uint32_t vb = st + FKSZ;
#pragma unroll
        for (int kb = 0; kb < 4; kb++) {
            const uint32_t ko = kb * 32;
#pragma unroll
            for (int p = 0; p < 8; p++) {
                uint32_t bhF[2][2];
                uint32_t va = vb + vLane + p * (16 * FVROW) + ko;
                LDSM_X4(bhF[0][0], bhF[0][1], bhF[1][0], bhF[1][1], va);
#pragma unroll
                for (int q = 0; q < 2; q++) {
                    int nb = 2 * p + q;
                    MMA16816(oacc[nb], ph[kb], bhF[q]);
                    MMA16816(oacc[nb], pl[kb], bhF[q]);
                }
            }
        }

        __syncthreads();
        if (j + 2 < NKVT)
            flash_load_stage(sbase, tid, j + 2, Kh, Vh);
    }

    // write ctx fp16 hi/lo token-major: [b*S+s][h*128+d]
    const int b = bh >> 4;
    const int h = bh & 15;
    const float inv0 = 1.0f / l0;
    const float inv1 = 1.0f / l1;
    const int s0r = q0 + wm + g;
    size_t idx0 = ((size_t)(b * SEQ + s0r)) * DMODEL + h * DK;
    size_t idx1 = ((size_t)(b * SEQ + s0r + 8)) * DMODEL + h * DK;
#pragma unroll
    for (int nb = 0; nb < 16; nb++) {
        int d = nb * 8 + t4 * 2;
        uint32_t hv, lv;
        split2(oacc[nb][0] * inv0, oacc[nb][1] * inv0, hv, lv);
        *(uint32_t*)&CH[idx0 + d] = hv;
        *(uint32_t*)&CL[idx0 + d] = lv;
        split2(oacc[nb][2] * inv1, oacc[nb][3] * inv1, hv, lv);
        *(uint32_t*)&CH[idx1 + d] = hv;
        *(uint32_t*)&CL[idx1 + d] = lv;
    }
}

// ---------------------------------------------------------------------------
// Launch
// ---------------------------------------------------------------------------
extern "C" void kernel_launch(void* const* d_in, const int* in_sizes, int n_in,
                              void* d_out, int out_size)
{
    const float* x  = (const float*)d_in[0];
    const float* Wq = (const float*)d_in[1];
    const float* bq = (const float*)d_in[2];
    const float* Aq = (const float*)d_in[3];
    const float* Bq = (const float*)d_in[4];
    const float* Wk = (const float*)d_in[5];
    const float* bk = (const float*)d_in[6];
    const float* Ak = (const float*)d_in[7];
    const float* Bk = (const float*)d_in[8];
    const float* Wv = (const float*)d_in[9];
    const float* bv = (const float*)d_in[10];
    const float* Av = (const float*)d_in[11];
    const float* Bv = (const float*)d_in[12];
    const float* Wo = (const float*)d_in[13];
    const float* bo = (const float*)d_in[14];
    const float* Ao = (const float*)d_in[15];
    const float* Bo = (const float*)d_in[16];
    float* out = (float*)d_out;

    float *pt, *pto;
    __half *pxhi, *pxlo, *pwhi, *pchi, *pclo;
    __half *pqhi, *pqlo, *pkhi, *pvhi, *pvthi;
    cudaGetSymbolAddress((void**)&pt,   g_t_qkv);
    cudaGetSymbolAddress((void**)&pto,  g_t_o);
    cudaGetSymbolAddress((void**)&pxhi, g_xhi);
    cudaGetSymbolAddress((void**)&pxlo, g_xlo);
    cudaGetSymbolAddress((void**)&pwhi, g_whi);
    cudaGetSymbolAddress((void**)&pchi, g_chi);
    cudaGetSymbolAddress((void**)&pclo, g_clo);
    cudaGetSymbolAddress((void**)&pqhi, g_qhi);
    cudaGetSymbolAddress((void**)&pqlo, g_qlo);
    cudaGetSymbolAddress((void**)&pkhi, g_khi);
    cudaGetSymbolAddress((void**)&pvhi, g_vhi);
    cudaGetSymbolAddress((void**)&pvthi, g_vthi);

    cudaFuncSetAttribute(gemm_mma_kernel<0>,
                         cudaFuncAttributeMaxDynamicSharedMemorySize, GEMM_SMEM);
    cudaFuncSetAttribute(gemm_mma_kernel<1>,
                         cudaFuncAttributeMaxDynamicSharedMemorySize, GEMM_SMEM);
    cudaFuncSetAttribute(flash_mma_kernel,
                         cudaFuncAttributeMaxDynamicSharedMemorySize, FLASH_SMEM);

    const size_t WSZ = (size_t)DMODEL * DMODEL;
    const int nX4 = MTOT * DMODEL / 4;
    const int nW4 = (int)(WSZ / 4);
    const int sg  = 256;

    // 1) Splits (x hi/lo; weights hi only)
    split_kernel<<<(nX4 + sg - 1) / sg, sg>>>(x, pxhi, pxlo, nX4);
    split_hi_kernel<<<(nW4 + sg - 1) / sg, sg>>>(Wq, pwhi + 0 * WSZ, nW4);
    split_hi_kernel<<<(nW4 + sg - 1) / sg, sg>>>(Wk, pwhi + 1 * WSZ, nW4);
    split_hi_kernel<<<(nW4 + sg - 1) / sg, sg>>>(Wv, pwhi + 2 * WSZ, nW4);
    split_hi_kernel<<<(nW4 + sg - 1) / sg, sg>>>(Wo, pwhi + 3 * WSZ, nW4);

    // 2) LoRA intermediates (q|k|v)
    lora_kernel<24><<<MTOT / 16, 256>>>(x, Aq, Ak, Av, pt);

    // 3) FUSED QKV projection (K, V write hi only)
    dim3 gQKV(3 * DMODEL / 128, MTOT / 128);   // (48, 32)
    gemm_mma_kernel<1><<<gQKV, 256, GEMM_SMEM>>>(
        pxhi, pxlo, pwhi,
        bq, bk, bv, pt, Bq, Bk, Bv,
        nullptr,
        pqhi, pqlo, pkhi, nullptr, pvhi, nullptr, 24);

    // 4) V transpose (hi only)
    dim3 tgrid(SEQ / 64, DK / 64, NBH);
    vtrans_kernel<<<tgrid, 256>>>(pvhi, pvthi);

    // 5) Flash attention -> ctx fp16 hi/lo
    dim3 fgrid(SEQ / 128, NBH);
    flash_mma_kernel<<<fgrid, 256, FLASH_SMEM>>>(pqhi, pqlo, pkhi, pvthi,
                                                 pchi, pclo);

    // 6) Output projection (ctx consumed directly as fp16 hi/lo)
    lora_h_kernel<8><<<MTOT / 16, 256>>>(pchi, pclo, Ao, pto);
    dim3 gO(DMODEL / 128, MTOT / 128);         // (16, 32)
    gemm_mma_kernel<0><<<gO, 256, GEMM_SMEM>>>(
        pchi, pclo, pwhi + 3 * WSZ,
        bo, bo, bo, pto, Bo, Bo, Bo,
        out,
        nullptr, nullptr, nullptr, nullptr, nullptr, nullptr, 8);
}